// round 4
// baseline (speedup 1.0000x reference)
#include <cuda_runtime.h>
#include <mma.h>

using namespace nvcuda;

#define NWIN 4096       // 4 * 32 * 32 windows
#define CCH  192
#define NH   6
#define NTHREADS 256    // 8 warps, 2 CTAs/SM

#define XS_LD  204      // x augmented to 200 cols (192 + ones-block)
#define QK2_LD 100      // per-head q|k|v (96 cols)
#define AL_LD  68       // logits 64 cols

#define SMEM_FLOATS (64*XS_LD + 64*QK2_LD + 64*AL_LD)
#define SMEM_BYTES  (SMEM_FLOATS * 4)   // 95232 B -> 2 CTAs/SM

// packed qkv weights (+bias row, scale folded into q):
// [h(6)][nt(6)][kt(25)][r(8)][c(16)]
__device__ float g_qkvw_packed[6 * 6 * 25 * 128];
// packed proj weights: [h(6)][nt(12)][kt(4)][r(8)][c(16)]
__device__ float g_projw_packed[6 * 12 * 4 * 128];

__global__ void repack_kernel(const float* __restrict__ qkv_w,
                              const float* __restrict__ qkv_b,
                              const float* __restrict__ proj_w)
{
    int i = blockIdx.x * blockDim.x + threadIdx.x;
    const int NQ = 6 * 6 * 25 * 128;     // 115200
    const float scale = 0.17677669529663687f; // 1/sqrt(32)
    if (i < NQ) {
        int c  = i & 15;
        int r  = (i >> 4) & 7;
        int t  = i >> 7;              // ((h*6 + nt)*25 + kt)
        int kt = t % 25;  t /= 25;
        int nt = t % 6;
        int h  = t / 6;
        int blk  = nt >> 1;           // 0=q,1=k,2=v
        int wrow = blk * 192 + h * 32 + (nt & 1) * 16 + c;
        float v;
        if (kt < 24) v = qkv_w[wrow * CCH + kt * 8 + r];
        else         v = (r == 0) ? qkv_b[wrow] : 0.0f;   // bias row (x aug col = 1)
        if (blk == 0) v *= scale;
        g_qkvw_packed[i] = wmma::__float_to_tf32(v);
    } else if (i < NQ + 6 * 12 * 4 * 128) {
        int j  = i - NQ;
        int c  = j & 15;
        int r  = (j >> 4) & 7;
        int t  = j >> 7;              // ((h*12 + nt)*4 + kt)
        int kt = t % 4;  t /= 4;
        int nt = t % 12;
        int h  = t / 12;
        g_projw_packed[j] =
            wmma::__float_to_tf32(proj_w[(nt * 16 + c) * CCH + h * 32 + kt * 8 + r]);
    }
}

__global__ __launch_bounds__(NTHREADS, 2)
void win_attn_kernel(const float* __restrict__ x,
                     const float* __restrict__ proj_b,
                     const float* __restrict__ bias,
                     float* __restrict__ out)
{
    extern __shared__ float smem[];
    float* xs   = smem;                       // [64][XS_LD]  x window (augmented)
    float* qkvh = xs + 64 * XS_LD;            // [64][QK2_LD] per-head q|k|v; q-region reused for AV
    float* als  = qkvh + 64 * QK2_LD;         // [64][AL_LD]  logits / probs

    const int tid = threadIdx.x;
    const int wid = tid >> 5;                 // 0..7
    const int mt    = wid & 3;                // row-stripe (all phases)
    const int whalf = wid >> 2;               // 0..1

    const int w   = blockIdx.x;
    const int b   = w >> 10;
    const int rem = w & 1023;
    const int wh  = rem >> 5;
    const int ww  = rem & 31;

    // ---- load x window (64 x 192) + augmentation cols ----
    {
        const float* xb = x + (size_t)b * 65536 * CCH;
        for (int i = tid; i < 64 * 48; i += NTHREADS) {
            int r  = i / 48;
            int c4 = i % 48;
            int iy = wh * 8 + (r >> 3);
            int ix = ww * 8 + (r & 7);
            float4 v = *(const float4*)(xb + (size_t)(iy * 256 + ix) * CCH + c4 * 4);
            v.x = wmma::__float_to_tf32(v.x);
            v.y = wmma::__float_to_tf32(v.y);
            v.z = wmma::__float_to_tf32(v.z);
            v.w = wmma::__float_to_tf32(v.w);
            *(float4*)(xs + r * XS_LD + c4 * 4) = v;
        }
        // aug cols 192..199: col192 = 1, rest 0 (bias row selector)
        for (int i = tid; i < 64 * 2; i += NTHREADS) {
            int r  = i >> 1;
            int c4 = i & 1;
            float4 v = (c4 == 0) ? make_float4(1.0f, 0.0f, 0.0f, 0.0f)
                                 : make_float4(0.0f, 0.0f, 0.0f, 0.0f);
            *(float4*)(xs + r * XS_LD + 192 + c4 * 4) = v;
        }
    }

    // persistent proj accumulators: warp owns (mt, nt in [6*whalf, 6*whalf+6))
    wmma::fragment<wmma::accumulator,16,16,8,float> pacc[6];
#pragma unroll
    for (int i = 0; i < 6; ++i) wmma::fill_fragment(pacc[i], 0.0f);

    __syncthreads();

    // ================= per-head pipeline =================
    for (int h = 0; h < NH; ++h) {
        // ---- GEMM1h: qkvh(64x96) = x_aug(64x200) @ Wh_aug^T (bias+scale folded) ----
        {
            wmma::fragment<wmma::accumulator,16,16,8,float> acc[3];
#pragma unroll
            for (int i = 0; i < 3; ++i) wmma::fill_fragment(acc[i], 0.0f);
            const float* wp = g_qkvw_packed + ((h * 6 + 3 * whalf) * 25) * 128;
#pragma unroll 5
            for (int kt = 0; kt < 25; ++kt) {
                wmma::fragment<wmma::matrix_a,16,16,8,wmma::precision::tf32,wmma::row_major> af;
                wmma::load_matrix_sync(af, xs + mt * 16 * XS_LD + kt * 8, XS_LD);
#pragma unroll
                for (int i = 0; i < 3; ++i) {
                    wmma::fragment<wmma::matrix_b,16,16,8,wmma::precision::tf32,wmma::row_major> bf;
                    wmma::load_matrix_sync(bf, wp + (i * 25 + kt) * 128, 16);
                    wmma::mma_sync(acc[i], af, bf, acc[i]);
                }
            }
#pragma unroll
            for (int i = 0; i < 3; ++i)
                wmma::store_matrix_sync(qkvh + mt * 16 * QK2_LD + (3 * whalf + i) * 16,
                                        acc[i], QK2_LD, wmma::mem_row_major);
        }
        __syncthreads();

        // ---- logits: als = q_scaled @ k^T + bias (bias preloaded into acc) ----
        {
            wmma::fragment<wmma::accumulator,16,16,8,float> acc[2];
#pragma unroll
            for (int n = 0; n < 2; ++n)
                wmma::load_matrix_sync(acc[n],
                    bias + (size_t)h * 4096 + mt * 16 * 64 + (2 * whalf + n) * 16, 64,
                    wmma::mem_row_major);
#pragma unroll
            for (int kt = 0; kt < 4; ++kt) {
                wmma::fragment<wmma::matrix_a,16,16,8,wmma::precision::tf32,wmma::row_major> af;
                wmma::load_matrix_sync(af, qkvh + mt * 16 * QK2_LD + kt * 8, QK2_LD);
#pragma unroll
                for (int n = 0; n < 2; ++n) {
                    wmma::fragment<wmma::matrix_b,16,16,8,wmma::precision::tf32,wmma::col_major> bf;
                    wmma::load_matrix_sync(bf,
                        qkvh + (2 * whalf + n) * 16 * QK2_LD + 32 + kt * 8, QK2_LD);
                    wmma::mma_sync(acc[n], af, bf, acc[n]);
                }
            }
#pragma unroll
            for (int n = 0; n < 2; ++n)
                wmma::store_matrix_sync(als + mt * 16 * AL_LD + (2 * whalf + n) * 16,
                                        acc[n], AL_LD, wmma::mem_row_major);
        }
        __syncthreads();

        // ---- softmax: 64 rows x 64 cols, 4 threads/row ----
        {
            int r  = tid >> 2;
            int l4 = tid & 3;
            float* row = als + r * AL_LD + l4 * 16;
            float vals[16];
            float mx = -1e30f;
#pragma unroll
            for (int i = 0; i < 4; ++i) {
                float4 v = *(float4*)(row + i * 4);
                vals[i*4+0] = v.x; vals[i*4+1] = v.y; vals[i*4+2] = v.z; vals[i*4+3] = v.w;
                mx = fmaxf(mx, fmaxf(fmaxf(v.x, v.y), fmaxf(v.z, v.w)));
            }
            mx = fmaxf(mx, __shfl_xor_sync(0xffffffffu, mx, 1));
            mx = fmaxf(mx, __shfl_xor_sync(0xffffffffu, mx, 2));
            float s = 0.0f;
#pragma unroll
            for (int i = 0; i < 16; ++i) {
                float e = __expf(vals[i] - mx);
                vals[i] = e;
                s += e;
            }
            s += __shfl_xor_sync(0xffffffffu, s, 1);
            s += __shfl_xor_sync(0xffffffffu, s, 2);
            float inv = 1.0f / s;
#pragma unroll
            for (int i = 0; i < 4; ++i) {
                float4 v;
                v.x = vals[i*4+0] * inv;
                v.y = vals[i*4+1] * inv;
                v.z = vals[i*4+2] * inv;
                v.w = vals[i*4+3] * inv;
                *(float4*)(row + i * 4) = v;
            }
        }
        __syncthreads();

        // ---- AV: av(64x32) = probs(64x64) @ v(64x32) -> qkvh q-region (dead) ----
        {
            wmma::fragment<wmma::accumulator,16,16,8,float> acc;
            wmma::fill_fragment(acc, 0.0f);
#pragma unroll
            for (int kt = 0; kt < 8; ++kt) {
                wmma::fragment<wmma::matrix_a,16,16,8,wmma::precision::tf32,wmma::row_major> af;
                wmma::fragment<wmma::matrix_b,16,16,8,wmma::precision::tf32,wmma::row_major> bf;
                wmma::load_matrix_sync(af, als + mt * 16 * AL_LD + kt * 8, AL_LD);
                wmma::load_matrix_sync(bf, qkvh + kt * 8 * QK2_LD + 64 + whalf * 16, QK2_LD);
                wmma::mma_sync(acc, af, bf, acc);
            }
            wmma::store_matrix_sync(qkvh + mt * 16 * QK2_LD + whalf * 16, acc,
                                    QK2_LD, wmma::mem_row_major);
        }
        __syncthreads();

        // ---- proj-accum: pacc[nt] += av(64x32) @ Wh_proj^T tiles ----
        {
            const float* wp = g_projw_packed + ((h * 12 + 6 * whalf) * 4) * 128;
#pragma unroll
            for (int kt = 0; kt < 4; ++kt) {
                wmma::fragment<wmma::matrix_a,16,16,8,wmma::precision::tf32,wmma::row_major> af;
                wmma::load_matrix_sync(af, qkvh + mt * 16 * QK2_LD + kt * 8, QK2_LD);
#pragma unroll
                for (int n = 0; n < 6; ++n) {
                    wmma::fragment<wmma::matrix_b,16,16,8,wmma::precision::tf32,wmma::row_major> bf;
                    wmma::load_matrix_sync(bf, wp + (n * 4 + kt) * 128, 16);
                    wmma::mma_sync(pacc[n], af, bf, pacc[n]);
                }
            }
        }
        __syncthreads();   // qkvh reused by next head's GEMM1
    }

    // ---- dump proj accumulators into xs (dead), then epilogue ----
#pragma unroll
    for (int n = 0; n < 6; ++n)
        wmma::store_matrix_sync(xs + mt * 16 * XS_LD + (6 * whalf + n) * 16, pacc[n],
                                XS_LD, wmma::mem_row_major);
    __syncthreads();

    {
        float* ob = out + (size_t)b * 65536 * CCH;
        for (int i = tid; i < 64 * 48; i += NTHREADS) {
            int r  = i / 48;
            int c4 = i % 48;
            float4 v  = *(float4*)(xs + r * XS_LD + c4 * 4);
            float4 pb = *(const float4*)(proj_b + c4 * 4);
            v.x += pb.x; v.y += pb.y; v.z += pb.z; v.w += pb.w;
            int iy = wh * 8 + (r >> 3);
            int ix = ww * 8 + (r & 7);
            *(float4*)(ob + (size_t)(iy * 256 + ix) * CCH + c4 * 4) = v;
        }
    }
}

extern "C" void kernel_launch(void* const* d_in, const int* in_sizes, int n_in,
                              void* d_out, int out_size)
{
    const float* x      = (const float*)d_in[0];
    const float* qkv_w  = (const float*)d_in[1];
    const float* qkv_b  = (const float*)d_in[2];
    const float* proj_w = (const float*)d_in[3];
    const float* proj_b = (const float*)d_in[4];
    const float* bias   = (const float*)d_in[5];
    float* out = (float*)d_out;

    repack_kernel<<<(152064 + 255) / 256, 256>>>(qkv_w, qkv_b, proj_w);

    cudaFuncSetAttribute(win_attn_kernel,
                         cudaFuncAttributeMaxDynamicSharedMemorySize, SMEM_BYTES);
    win_attn_kernel<<<NWIN, NTHREADS, SMEM_BYTES>>>(x, proj_b, bias, out);
}

// round 5
// speedup vs baseline: 2.1110x; 2.1110x over previous
#include <cuda_runtime.h>
#include <mma.h>

using namespace nvcuda;

#define NWIN 4096       // 4 * 32 * 32 windows
#define CCH  192
#define NTHREADS 576    // 18 warps

#define XS_LD  204      // x augmented to 200 cols
#define QK_LD  580      // qkv 576 cols
#define AL_LD  68       // probs 64 cols

#define SCR_FLOATS (64 * XS_LD)            // 13056 == 3 * 64 * AL_LD
#define SMEM_FLOATS (64 * QK_LD + SCR_FLOATS)
#define SMEM_BYTES  (SMEM_FLOATS * 4)      // 200704 B

// packed qkv weights (+bias row at kt=24, softmax scale folded into q):
// flat [gnt(36)][kt(25)][r(8)][c(16)], gnt = h*6 + nt_local
__device__ float g_qkvw_packed[36 * 25 * 128];
// packed proj weights: [nt(12)][kt(24)][r(8)][c(16)]
__device__ float g_projw_packed[12 * 24 * 128];

__global__ void repack_kernel(const float* __restrict__ qkv_w,
                              const float* __restrict__ qkv_b,
                              const float* __restrict__ proj_w)
{
    int i = blockIdx.x * blockDim.x + threadIdx.x;
    const int NQ = 36 * 25 * 128;          // 115200
    const float scale = 0.17677669529663687f; // 1/sqrt(32)
    if (i < NQ) {
        int c  = i & 15;
        int r  = (i >> 4) & 7;
        int t  = i >> 7;               // gnt*25 + kt
        int kt  = t % 25;
        int gnt = t / 25;
        int h   = gnt / 6;
        int ntl = gnt % 6;
        int blk  = ntl >> 1;           // 0=q,1=k,2=v
        int wrow = blk * 192 + h * 32 + (ntl & 1) * 16 + c;
        float v;
        if (kt < 24) v = qkv_w[wrow * CCH + kt * 8 + r];
        else         v = (r == 0) ? qkv_b[wrow] : 0.0f;   // bias row
        if (blk == 0) v *= scale;
        g_qkvw_packed[i] = wmma::__float_to_tf32(v);
    } else if (i < NQ + 12 * 24 * 128) {
        int j  = i - NQ;
        int c  = j & 15;
        int r  = (j >> 4) & 7;
        int t  = j >> 7;               // nt*24 + kt
        int kt = t % 24;
        int nt = t / 24;
        g_projw_packed[j] =
            wmma::__float_to_tf32(proj_w[(nt * 16 + c) * CCH + kt * 8 + r]);
    }
}

__device__ __forceinline__ void round_acc(
    wmma::fragment<wmma::accumulator,16,16,8,float>& a) {
#pragma unroll
    for (int e = 0; e < a.num_elements; ++e) a.x[e] = wmma::__float_to_tf32(a.x[e]);
}

__global__ __launch_bounds__(NTHREADS, 1)
void win_attn_kernel(const float* __restrict__ x,
                     const float* __restrict__ proj_b,
                     const float* __restrict__ bias,
                     float* __restrict__ out)
{
    extern __shared__ float smem[];
    float* qkvs = smem;                   // [64][QK_LD] q|k|v; q cols reused for AV out
    float* scr  = smem + 64 * QK_LD;      // x window (GEMM1) / 3 probs buffers / proj out

    const int tid = threadIdx.x;
    const int wid = tid >> 5;             // 0..17

    const int w   = blockIdx.x;
    const int b   = w >> 10;
    const int rem = w & 1023;
    const int wh  = rem >> 5;
    const int ww  = rem & 31;

    // ---- load x window (64 x 192) + augmentation cols, tf32-rounded ----
    {
        const float* xb = x + (size_t)b * 65536 * CCH;
        for (int i = tid; i < 64 * 48; i += NTHREADS) {
            int r  = i / 48;
            int c4 = i % 48;
            int iy = wh * 8 + (r >> 3);
            int ix = ww * 8 + (r & 7);
            float4 v = *(const float4*)(xb + (size_t)(iy * 256 + ix) * CCH + c4 * 4);
            v.x = wmma::__float_to_tf32(v.x);
            v.y = wmma::__float_to_tf32(v.y);
            v.z = wmma::__float_to_tf32(v.z);
            v.w = wmma::__float_to_tf32(v.w);
            *(float4*)(scr + r * XS_LD + c4 * 4) = v;
        }
        for (int i = tid; i < 128; i += NTHREADS) {
            int r  = i >> 1;
            int c4 = i & 1;
            float4 v = (c4 == 0) ? make_float4(1.0f, 0.0f, 0.0f, 0.0f)
                                 : make_float4(0.0f, 0.0f, 0.0f, 0.0f);
            *(float4*)(scr + r * XS_LD + 192 + c4 * 4) = v;
        }
    }
    __syncthreads();

    // ---- GEMM1: qkv = x_aug(64x200) @ W_aug^T; warp owns 2 nt tiles x 4 mt ----
    {
        wmma::fragment<wmma::accumulator,16,16,8,float> acc[2][4];
#pragma unroll
        for (int i = 0; i < 2; ++i)
#pragma unroll
            for (int j = 0; j < 4; ++j) wmma::fill_fragment(acc[i][j], 0.0f);

        const int gnt0 = wid * 2;
        for (int kt = 0; kt < 25; ++kt) {
            wmma::fragment<wmma::matrix_a,16,16,8,wmma::precision::tf32,wmma::row_major> af[4];
#pragma unroll
            for (int j = 0; j < 4; ++j)
                wmma::load_matrix_sync(af[j], scr + j * 16 * XS_LD + kt * 8, XS_LD);
#pragma unroll
            for (int i = 0; i < 2; ++i) {
                wmma::fragment<wmma::matrix_b,16,16,8,wmma::precision::tf32,wmma::row_major> bf;
                wmma::load_matrix_sync(bf, g_qkvw_packed + ((gnt0 + i) * 25 + kt) * 128, 16);
#pragma unroll
                for (int j = 0; j < 4; ++j)
                    wmma::mma_sync(acc[i][j], af[j], bf, acc[i][j]);
            }
        }
#pragma unroll
        for (int i = 0; i < 2; ++i) {
            int gnt = gnt0 + i;
            int h   = gnt / 6;
            int ntl = gnt % 6;
            int col = (ntl >> 1) * 192 + h * 32 + (ntl & 1) * 16;
#pragma unroll
            for (int j = 0; j < 4; ++j) {
                round_acc(acc[i][j]);
                wmma::store_matrix_sync(qkvs + j * 16 * QK_LD + col, acc[i][j],
                                        QK_LD, wmma::mem_row_major);
            }
        }
    }
    __syncthreads();

    // ================= attention: 3 independent 4-warp head-sets =================
    // set s (warps 6s..6s+3, i.e. stid<128) handles heads {s, s+3}.
    {
        const int set  = wid / 6;
        const int stid = tid - set * 192;
        float* probs = scr + set * 64 * AL_LD;

        if (stid < 128) {
            const int mt = stid >> 5;          // warp-in-set 0..3 = row stripe
#pragma unroll
            for (int hh = 0; hh < 2; ++hh) {
                const int h  = set + 3 * hh;
                const int qo = h * 32;
                const int ko = 192 + h * 32;
                const int vo = 384 + h * 32;

                // ---- logits: probs = q_scaled @ k^T + bias ----
                {
                    wmma::fragment<wmma::accumulator,16,16,8,float> acc[4];
#pragma unroll
                    for (int nt = 0; nt < 4; ++nt)
                        wmma::load_matrix_sync(acc[nt],
                            bias + (size_t)h * 4096 + mt * 16 * 64 + nt * 16, 64,
                            wmma::mem_row_major);
#pragma unroll
                    for (int kt = 0; kt < 4; ++kt) {
                        wmma::fragment<wmma::matrix_a,16,16,8,wmma::precision::tf32,wmma::row_major> af;
                        wmma::load_matrix_sync(af, qkvs + mt * 16 * QK_LD + qo + kt * 8, QK_LD);
#pragma unroll
                        for (int nt = 0; nt < 4; ++nt) {
                            wmma::fragment<wmma::matrix_b,16,16,8,wmma::precision::tf32,wmma::col_major> bf;
                            wmma::load_matrix_sync(bf, qkvs + nt * 16 * QK_LD + ko + kt * 8, QK_LD);
                            wmma::mma_sync(acc[nt], af, bf, acc[nt]);
                        }
                    }
#pragma unroll
                    for (int nt = 0; nt < 4; ++nt)
                        wmma::store_matrix_sync(probs + mt * 16 * AL_LD + nt * 16, acc[nt],
                                                AL_LD, wmma::mem_row_major);
                }
                asm volatile("bar.sync %0, 128;" :: "r"(set + 1) : "memory");

                // ---- softmax: 64 rows x 64 cols, 2 threads/row ----
                {
                    int r    = stid >> 1;
                    int half = stid & 1;
                    float* row = probs + r * AL_LD + half * 32;
                    float vals[32];
                    float mx = -1e30f;
#pragma unroll
                    for (int i = 0; i < 8; ++i) {
                        float4 v = *(float4*)(row + i * 4);
                        vals[i*4+0] = v.x; vals[i*4+1] = v.y;
                        vals[i*4+2] = v.z; vals[i*4+3] = v.w;
                        mx = fmaxf(mx, fmaxf(fmaxf(v.x, v.y), fmaxf(v.z, v.w)));
                    }
                    mx = fmaxf(mx, __shfl_xor_sync(0xffffffffu, mx, 1));
                    float s = 0.0f;
#pragma unroll
                    for (int i = 0; i < 32; ++i) {
                        float e = __expf(vals[i] - mx);
                        vals[i] = e;
                        s += e;
                    }
                    s += __shfl_xor_sync(0xffffffffu, s, 1);
                    float inv = 1.0f / s;
#pragma unroll
                    for (int i = 0; i < 8; ++i) {
                        float4 v;
                        v.x = wmma::__float_to_tf32(vals[i*4+0] * inv);
                        v.y = wmma::__float_to_tf32(vals[i*4+1] * inv);
                        v.z = wmma::__float_to_tf32(vals[i*4+2] * inv);
                        v.w = wmma::__float_to_tf32(vals[i*4+3] * inv);
                        *(float4*)(row + i * 4) = v;
                    }
                }
                asm volatile("bar.sync %0, 128;" :: "r"(set + 1) : "memory");

                // ---- AV: probs(64x64) @ v(64x32) -> q-region cols [qo, qo+32) ----
                {
                    wmma::fragment<wmma::accumulator,16,16,8,float> acc[2];
#pragma unroll
                    for (int nt = 0; nt < 2; ++nt) wmma::fill_fragment(acc[nt], 0.0f);
#pragma unroll
                    for (int kt = 0; kt < 8; ++kt) {
                        wmma::fragment<wmma::matrix_a,16,16,8,wmma::precision::tf32,wmma::row_major> af;
                        wmma::load_matrix_sync(af, probs + mt * 16 * AL_LD + kt * 8, AL_LD);
#pragma unroll
                        for (int nt = 0; nt < 2; ++nt) {
                            wmma::fragment<wmma::matrix_b,16,16,8,wmma::precision::tf32,wmma::row_major> bf;
                            wmma::load_matrix_sync(bf, qkvs + kt * 8 * QK_LD + vo + nt * 16, QK_LD);
                            wmma::mma_sync(acc[nt], af, bf, acc[nt]);
                        }
                    }
#pragma unroll
                    for (int nt = 0; nt < 2; ++nt) {
                        round_acc(acc[nt]);
                        wmma::store_matrix_sync(qkvs + mt * 16 * QK_LD + qo + nt * 16,
                                                acc[nt], QK_LD, wmma::mem_row_major);
                    }
                }
                // next head's logits store is program-ordered after this AV (same warps)
            }
        }
    }
    __syncthreads();

    // ---- proj: scr(64x192) = attn_out(64x192) @ proj_w^T ; warps 0..11, nt=wid ----
    if (wid < 12) {
        wmma::fragment<wmma::accumulator,16,16,8,float> acc[4];
#pragma unroll
        for (int j = 0; j < 4; ++j) wmma::fill_fragment(acc[j], 0.0f);
        for (int kt = 0; kt < 24; ++kt) {
            wmma::fragment<wmma::matrix_b,16,16,8,wmma::precision::tf32,wmma::row_major> bf;
            wmma::load_matrix_sync(bf, g_projw_packed + (wid * 24 + kt) * 128, 16);
#pragma unroll
            for (int j = 0; j < 4; ++j) {
                wmma::fragment<wmma::matrix_a,16,16,8,wmma::precision::tf32,wmma::row_major> af;
                wmma::load_matrix_sync(af, qkvs + j * 16 * QK_LD + kt * 8, QK_LD);
                wmma::mma_sync(acc[j], af, bf, acc[j]);
            }
        }
#pragma unroll
        for (int j = 0; j < 4; ++j)
            wmma::store_matrix_sync(scr + j * 16 * XS_LD + wid * 16, acc[j], XS_LD,
                                    wmma::mem_row_major);
    }
    __syncthreads();

    // ---- epilogue: add proj_b, scatter to (B, H*W, C) ----
    {
        float* ob = out + (size_t)b * 65536 * CCH;
        for (int i = tid; i < 64 * 48; i += NTHREADS) {
            int r  = i / 48;
            int c4 = i % 48;
            float4 v  = *(float4*)(scr + r * XS_LD + c4 * 4);
            float4 pb = *(const float4*)(proj_b + c4 * 4);
            v.x += pb.x; v.y += pb.y; v.z += pb.z; v.w += pb.w;
            int iy = wh * 8 + (r >> 3);
            int ix = ww * 8 + (r & 7);
            *(float4*)(ob + (size_t)(iy * 256 + ix) * CCH + c4 * 4) = v;
        }
    }
}

extern "C" void kernel_launch(void* const* d_in, const int* in_sizes, int n_in,
                              void* d_out, int out_size)
{
    const float* x      = (const float*)d_in[0];
    const float* qkv_w  = (const float*)d_in[1];
    const float* qkv_b  = (const float*)d_in[2];
    const float* proj_w = (const float*)d_in[3];
    const float* proj_b = (const float*)d_in[4];
    const float* bias   = (const float*)d_in[5];
    float* out = (float*)d_out;

    repack_kernel<<<(152064 + 255) / 256, 256>>>(qkv_w, qkv_b, proj_w);

    cudaFuncSetAttribute(win_attn_kernel,
                         cudaFuncAttributeMaxDynamicSharedMemorySize, SMEM_BYTES);
    win_attn_kernel<<<NWIN, NTHREADS, SMEM_BYTES>>>(x, proj_b, bias, out);
}

// round 7
// speedup vs baseline: 2.3256x; 1.1017x over previous
#include <cuda_runtime.h>
#include <mma.h>

using namespace nvcuda;

#define NWIN 4096       // 4 * 32 * 32 windows
#define CCH  192
#define NTHREADS 384    // 12 warps

#define XS_LD  204      // x augmented to 200 cols
#define QK_LD  580      // qkv 576 cols
#define PR_LD  68       // per-warp probs stripe: 16 rows x 68

#define SCR_FLOATS (64 * XS_LD)            // 13056 == 12 * 16 * PR_LD
#define SMEM_FLOATS (64 * QK_LD + SCR_FLOATS)
#define SMEM_BYTES  (SMEM_FLOATS * 4)      // 200704 B

// packed qkv weights (+bias row at kt=24, softmax scale folded into q):
// flat [gnt(36)][kt(25)][r(8)][c(16)], gnt = h*6 + nt_local
__device__ float g_qkvw_packed[36 * 25 * 128];
// packed proj weights: [nt(12)][kt(24)][r(8)][c(16)]
__device__ float g_projw_packed[12 * 24 * 128];

__global__ void repack_kernel(const float* __restrict__ qkv_w,
                              const float* __restrict__ qkv_b,
                              const float* __restrict__ proj_w)
{
    int i = blockIdx.x * blockDim.x + threadIdx.x;
    const int NQ = 36 * 25 * 128;          // 115200
    const float scale = 0.17677669529663687f; // 1/sqrt(32)
    if (i < NQ) {
        int c  = i & 15;
        int r  = (i >> 4) & 7;
        int t  = i >> 7;               // gnt*25 + kt
        int kt  = t % 25;
        int gnt = t / 25;
        int h   = gnt / 6;
        int ntl = gnt % 6;
        int blk  = ntl >> 1;           // 0=q,1=k,2=v
        int wrow = blk * 192 + h * 32 + (ntl & 1) * 16 + c;
        float v;
        if (kt < 24) v = qkv_w[wrow * CCH + kt * 8 + r];
        else         v = (r == 0) ? qkv_b[wrow] : 0.0f;   // bias row
        if (blk == 0) v *= scale;
        g_qkvw_packed[i] = wmma::__float_to_tf32(v);
    } else if (i < NQ + 12 * 24 * 128) {
        int j  = i - NQ;
        int c  = j & 15;
        int r  = (j >> 4) & 7;
        int t  = j >> 7;               // nt*24 + kt
        int kt = t % 24;
        int nt = t / 24;
        g_projw_packed[j] =
            wmma::__float_to_tf32(proj_w[(nt * 16 + c) * CCH + kt * 8 + r]);
    }
}

__device__ __forceinline__ void round_acc(
    wmma::fragment<wmma::accumulator,16,16,8,float>& a) {
#pragma unroll
    for (int e = 0; e < a.num_elements; ++e) a.x[e] = wmma::__float_to_tf32(a.x[e]);
}

__global__ __launch_bounds__(NTHREADS, 1)
void win_attn_kernel(const float* __restrict__ x,
                     const float* __restrict__ proj_b,
                     const float* __restrict__ bias,
                     float* __restrict__ out)
{
    extern __shared__ float smem[];
    float* qkvs = smem;                   // [64][QK_LD] q|k|v; q cols reused for AV out
    float* scr  = smem + 64 * QK_LD;      // x window / 12 warp-private probs stripes / proj out

    const int tid  = threadIdx.x;
    const int wid  = tid >> 5;            // 0..11
    const int lane = tid & 31;

    const int w   = blockIdx.x;
    const int b   = w >> 10;
    const int rem = w & 1023;
    const int wh  = rem >> 5;
    const int ww  = rem & 31;

    // ---- load x window (64 x 192) + augmentation cols, tf32-rounded ----
    {
        const float* xb = x + (size_t)b * 65536 * CCH;
        for (int i = tid; i < 64 * 48; i += NTHREADS) {
            int r  = i / 48;
            int c4 = i % 48;
            int iy = wh * 8 + (r >> 3);
            int ix = ww * 8 + (r & 7);
            float4 v = *(const float4*)(xb + (size_t)(iy * 256 + ix) * CCH + c4 * 4);
            v.x = wmma::__float_to_tf32(v.x);
            v.y = wmma::__float_to_tf32(v.y);
            v.z = wmma::__float_to_tf32(v.z);
            v.w = wmma::__float_to_tf32(v.w);
            *(float4*)(scr + r * XS_LD + c4 * 4) = v;
        }
        for (int i = tid; i < 128; i += NTHREADS) {
            int r  = i >> 1;
            int c4 = i & 1;
            float4 v = (c4 == 0) ? make_float4(1.0f, 0.0f, 0.0f, 0.0f)
                                 : make_float4(0.0f, 0.0f, 0.0f, 0.0f);
            *(float4*)(scr + r * XS_LD + 192 + c4 * 4) = v;
        }
    }
    __syncthreads();

    // ---- GEMM1: qkv = x_aug(64x200) @ W_aug^T (bias+scale folded).
    //      warp owns 3 gnt tiles x 4 mt; 25 kt steps (24 + bias row) ----
    {
        wmma::fragment<wmma::accumulator,16,16,8,float> acc[3][4];
#pragma unroll
        for (int i = 0; i < 3; ++i)
#pragma unroll
            for (int j = 0; j < 4; ++j) wmma::fill_fragment(acc[i][j], 0.0f);

        const int gnt0 = wid * 3;
        for (int kt = 0; kt < 25; ++kt) {
            wmma::fragment<wmma::matrix_a,16,16,8,wmma::precision::tf32,wmma::row_major> af[4];
#pragma unroll
            for (int j = 0; j < 4; ++j)
                wmma::load_matrix_sync(af[j], scr + j * 16 * XS_LD + kt * 8, XS_LD);
#pragma unroll
            for (int i = 0; i < 3; ++i) {
                wmma::fragment<wmma::matrix_b,16,16,8,wmma::precision::tf32,wmma::row_major> bf;
                wmma::load_matrix_sync(bf, g_qkvw_packed + ((gnt0 + i) * 25 + kt) * 128, 16);
#pragma unroll
                for (int j = 0; j < 4; ++j)
                    wmma::mma_sync(acc[i][j], af[j], bf, acc[i][j]);
            }
        }
#pragma unroll
        for (int i = 0; i < 3; ++i) {
            int gnt = gnt0 + i;
            int h   = gnt / 6;
            int ntl = gnt % 6;
            int col = (ntl >> 1) * 192 + h * 32 + (ntl & 1) * 16;
#pragma unroll
            for (int j = 0; j < 4; ++j) {
                round_acc(acc[i][j]);
                wmma::store_matrix_sync(qkvs + j * 16 * QK_LD + col, acc[i][j],
                                        QK_LD, wmma::mem_row_major);
            }
        }
    }
    __syncthreads();

    // ================= attention middle: BARRIER-FREE =================
    // warp wid -> (mt = wid&3 row-stripe, hset = wid>>2), heads {hset, hset+3}.
    // probs stripe (16 x PR_LD) is warp-private; softmax + AV read only what
    // this warp wrote. Only __syncwarp() between sub-steps.
    {
        const int mt   = wid & 3;
        const int hset = wid >> 2;          // 0..2
        float* probs = scr + wid * (16 * PR_LD);

#pragma unroll
        for (int hh = 0; hh < 2; ++hh) {
            const int h  = hset + 3 * hh;
            const int qo = h * 32;
            const int ko = 192 + h * 32;
            const int vo = 384 + h * 32;

            // ---- logits stripe: 16 rows x 64 cols, bias preloaded into acc ----
            {
                wmma::fragment<wmma::accumulator,16,16,8,float> acc[4];
#pragma unroll
                for (int nt = 0; nt < 4; ++nt)
                    wmma::load_matrix_sync(acc[nt],
                        bias + (size_t)h * 4096 + mt * 16 * 64 + nt * 16, 64,
                        wmma::mem_row_major);
#pragma unroll
                for (int kt = 0; kt < 4; ++kt) {
                    wmma::fragment<wmma::matrix_a,16,16,8,wmma::precision::tf32,wmma::row_major> af;
                    wmma::load_matrix_sync(af, qkvs + mt * 16 * QK_LD + qo + kt * 8, QK_LD);
#pragma unroll
                    for (int nt = 0; nt < 4; ++nt) {
                        wmma::fragment<wmma::matrix_b,16,16,8,wmma::precision::tf32,wmma::col_major> bf;
                        wmma::load_matrix_sync(bf, qkvs + nt * 16 * QK_LD + ko + kt * 8, QK_LD);
                        wmma::mma_sync(acc[nt], af, bf, acc[nt]);
                    }
                }
#pragma unroll
                for (int nt = 0; nt < 4; ++nt)
                    wmma::store_matrix_sync(probs + nt * 16, acc[nt], PR_LD,
                                            wmma::mem_row_major);
            }
            __syncwarp();

            // ---- softmax on own stripe: 16 rows, 2 lanes/row ----
            {
                int r    = lane >> 1;
                int half = lane & 1;
                float* row = probs + r * PR_LD + half * 32;
                float vals[32];
                float mx = -1e30f;
#pragma unroll
                for (int i = 0; i < 8; ++i) {
                    float4 v = *(float4*)(row + i * 4);
                    vals[i*4+0] = v.x; vals[i*4+1] = v.y;
                    vals[i*4+2] = v.z; vals[i*4+3] = v.w;
                    mx = fmaxf(mx, fmaxf(fmaxf(v.x, v.y), fmaxf(v.z, v.w)));
                }
                mx = fmaxf(mx, __shfl_xor_sync(0xffffffffu, mx, 1));
                float s = 0.0f;
#pragma unroll
                for (int i = 0; i < 32; ++i) {
                    float e = __expf(vals[i] - mx);
                    vals[i] = e;
                    s += e;
                }
                s += __shfl_xor_sync(0xffffffffu, s, 1);
                float inv = 1.0f / s;
#pragma unroll
                for (int i = 0; i < 8; ++i) {
                    float4 v;
                    v.x = wmma::__float_to_tf32(vals[i*4+0] * inv);
                    v.y = wmma::__float_to_tf32(vals[i*4+1] * inv);
                    v.z = wmma::__float_to_tf32(vals[i*4+2] * inv);
                    v.w = wmma::__float_to_tf32(vals[i*4+3] * inv);
                    *(float4*)(row + i * 4) = v;
                }
            }
            __syncwarp();

            // ---- AV stripe: probs(16x64) @ v(64x32) -> q-region rows mt, cols [qo,qo+32) ----
            {
                wmma::fragment<wmma::accumulator,16,16,8,float> acc[2];
#pragma unroll
                for (int nt = 0; nt < 2; ++nt) wmma::fill_fragment(acc[nt], 0.0f);
#pragma unroll
                for (int kt = 0; kt < 8; ++kt) {
                    wmma::fragment<wmma::matrix_a,16,16,8,wmma::precision::tf32,wmma::row_major> af;
                    wmma::load_matrix_sync(af, probs + kt * 8, PR_LD);
#pragma unroll
                    for (int nt = 0; nt < 2; ++nt) {
                        wmma::fragment<wmma::matrix_b,16,16,8,wmma::precision::tf32,wmma::row_major> bf;
                        wmma::load_matrix_sync(bf, qkvs + kt * 8 * QK_LD + vo + nt * 16, QK_LD);
                        wmma::mma_sync(acc[nt], af, bf, acc[nt]);
                    }
                }
#pragma unroll
                for (int nt = 0; nt < 2; ++nt) {
                    round_acc(acc[nt]);
                    wmma::store_matrix_sync(qkvs + mt * 16 * QK_LD + qo + nt * 16,
                                            acc[nt], QK_LD, wmma::mem_row_major);
                }
            }
            __syncwarp();   // probs stripe reused by next head
        }
    }
    __syncthreads();

    // ---- proj: scr(64x192) = attn_out(64x192) @ proj_w^T ; warp owns nt=wid ----
    {
        wmma::fragment<wmma::accumulator,16,16,8,float> acc[4];
#pragma unroll
        for (int j = 0; j < 4; ++j) wmma::fill_fragment(acc[j], 0.0f);
        for (int kt = 0; kt < 24; ++kt) {
            wmma::fragment<wmma::matrix_b,16,16,8,wmma::precision::tf32,wmma::row_major> bf;
            wmma::load_matrix_sync(bf, g_projw_packed + (wid * 24 + kt) * 128, 16);
#pragma unroll
            for (int j = 0; j < 4; ++j) {
                wmma::fragment<wmma::matrix_a,16,16,8,wmma::precision::tf32,wmma::row_major> af;
                wmma::load_matrix_sync(af, qkvs + j * 16 * QK_LD + kt * 8, QK_LD);
                wmma::mma_sync(acc[j], af, bf, acc[j]);
            }
        }
#pragma unroll
        for (int j = 0; j < 4; ++j)
            wmma::store_matrix_sync(scr + j * 16 * XS_LD + wid * 16, acc[j], XS_LD,
                                    wmma::mem_row_major);
    }
    __syncthreads();

    // ---- epilogue: add proj_b, scatter to (B, H*W, C) ----
    {
        float* ob = out + (size_t)b * 65536 * CCH;
        for (int i = tid; i < 64 * 48; i += NTHREADS) {
            int r  = i / 48;
            int c4 = i % 48;
            float4 v  = *(float4*)(scr + r * XS_LD + c4 * 4);
            float4 pb = *(const float4*)(proj_b + c4 * 4);
            v.x += pb.x; v.y += pb.y; v.z += pb.z; v.w += pb.w;
            int iy = wh * 8 + (r >> 3);
            int ix = ww * 8 + (r & 7);
            *(float4*)(ob + (size_t)(iy * 256 + ix) * CCH + c4 * 4) = v;
        }
    }
}

extern "C" void kernel_launch(void* const* d_in, const int* in_sizes, int n_in,
                              void* d_out, int out_size)
{
    const float* x      = (const float*)d_in[0];
    const float* qkv_w  = (const float*)d_in[1];
    const float* qkv_b  = (const float*)d_in[2];
    const float* proj_w = (const float*)d_in[3];
    const float* proj_b = (const float*)d_in[4];
    const float* bias   = (const float*)d_in[5];
    float* out = (float*)d_out;

    repack_kernel<<<(152064 + 255) / 256, 256>>>(qkv_w, qkv_b, proj_w);

    cudaFuncSetAttribute(win_attn_kernel,
                         cudaFuncAttributeMaxDynamicSharedMemorySize, SMEM_BYTES);
    win_attn_kernel<<<NWIN, NTHREADS, SMEM_BYTES>>>(x, proj_b, bias, out);
}

// round 8
// speedup vs baseline: 6.0287x; 2.5923x over previous
#include <cuda_runtime.h>
#include <cuda_fp16.h>
#include <mma.h>

using namespace nvcuda;

#define NWIN 4096       // 4 * 32 * 32 windows
#define CCH  192
#define NTHREADS 384    // 12 warps

// all strides in HALF elements
#define XS_LD  216      // x augmented to 208 cols (192 + 16 aug) + pad
#define QK_LD  584      // qkv 576 cols + pad; float view stride = 292
#define PR_LD  72       // per-warp probs stripe: 16 rows x 72

#define SCR_HALFS (64 * XS_LD)             // 13824 == 12 * 16 * PR_LD
#define SMEM_HALFS (64 * QK_LD + SCR_HALFS)
#define SMEM_BYTES (SMEM_HALFS * 2)        // 102400 B

// packed qkv weights as half, fragment-ready [16k][16n] tiles:
// [gnt(36)][kt(13)][256]; bias row at k==192 (scale folded into q)
__device__ __half g_qkvw_packed[36 * 13 * 256];
// packed proj weights: [nt(12)][kt(12)][256]
__device__ __half g_projw_packed[12 * 12 * 256];

__global__ void repack_kernel(const float* __restrict__ qkv_w,
                              const float* __restrict__ qkv_b,
                              const float* __restrict__ proj_w)
{
    int i = blockIdx.x * blockDim.x + threadIdx.x;
    const int NQ = 36 * 13 * 256;          // 119808
    const float scale = 0.17677669529663687f; // 1/sqrt(32)
    if (i < NQ) {
        int c  = i & 15;              // n col
        int r  = (i >> 4) & 15;       // k row within tile
        int t  = i >> 8;              // gnt*13 + kt
        int kt  = t % 13;
        int gnt = t / 13;
        int h   = gnt / 6;
        int ntl = gnt % 6;
        int blk  = ntl >> 1;          // 0=q,1=k,2=v
        int wrow = blk * 192 + h * 32 + (ntl & 1) * 16 + c;
        int k    = kt * 16 + r;
        float v;
        if (k < 192)       v = qkv_w[wrow * CCH + k];
        else if (k == 192) v = qkv_b[wrow];          // bias row (aug col = 1)
        else               v = 0.0f;
        if (blk == 0) v *= scale;
        g_qkvw_packed[i] = __float2half(v);
    } else if (i < NQ + 12 * 12 * 256) {
        int j  = i - NQ;
        int c  = j & 15;
        int r  = (j >> 4) & 15;
        int t  = j >> 8;              // nt*12 + kt
        int kt = t % 12;
        int nt = t / 12;
        g_projw_packed[j] = __float2half(proj_w[(nt * 16 + c) * CCH + kt * 16 + r]);
    }
}

using FragA   = wmma::fragment<wmma::matrix_a,16,16,16,__half,wmma::row_major>;
using FragBR  = wmma::fragment<wmma::matrix_b,16,16,16,__half,wmma::row_major>;
using FragBC  = wmma::fragment<wmma::matrix_b,16,16,16,__half,wmma::col_major>;
using FragCF  = wmma::fragment<wmma::accumulator,16,16,16,float>;
using FragCH  = wmma::fragment<wmma::accumulator,16,16,16,__half>;

// store a float accumulator to half memory (acc layouts match for m16n16k16)
__device__ __forceinline__ void store_acc_half(__half* ptr, int ld, const FragCF& f) {
    FragCH h;
#pragma unroll
    for (int e = 0; e < f.num_elements; ++e) h.x[e] = __float2half(f.x[e]);
    wmma::store_matrix_sync(ptr, h, ld, wmma::mem_row_major);
}

__global__ __launch_bounds__(NTHREADS, 1)
void win_attn_kernel(const float* __restrict__ x,
                     const float* __restrict__ proj_b,
                     const float* __restrict__ bias,
                     float* __restrict__ out)
{
    extern __shared__ __half smem[];
    __half* qkvs = smem;                  // [64][QK_LD] q|k|v half; later float proj out overlay
    __half* scr  = smem + 64 * QK_LD;     // x window / 12 warp-private probs stripes

    const int tid  = threadIdx.x;
    const int wid  = tid >> 5;            // 0..11
    const int lane = tid & 31;

    const int w   = blockIdx.x;
    const int b   = w >> 10;
    const int rem = w & 1023;
    const int wh  = rem >> 5;
    const int ww  = rem & 31;

    // ---- load x window (64 x 192) as half + augmentation cols ----
    {
        const float* xb = x + (size_t)b * 65536 * CCH;
        for (int i = tid; i < 64 * 48; i += NTHREADS) {
            int r  = i / 48;
            int c4 = i % 48;
            int iy = wh * 8 + (r >> 3);
            int ix = ww * 8 + (r & 7);
            float4 v = *(const float4*)(xb + (size_t)(iy * 256 + ix) * CCH + c4 * 4);
            __half2* d = (__half2*)(scr + r * XS_LD + c4 * 4);
            d[0] = __floats2half2_rn(v.x, v.y);
            d[1] = __floats2half2_rn(v.z, v.w);
        }
        // aug cols 192..207: col 192 = 1.0, rest 0
        for (int i = tid; i < 64 * 2; i += NTHREADS) {
            int r  = i >> 1;
            int g  = i & 1;
            __half2* d = (__half2*)(scr + r * XS_LD + 192 + g * 8);
            __half2 z = __floats2half2_rn(0.0f, 0.0f);
            d[0] = (g == 0) ? __floats2half2_rn(1.0f, 0.0f) : z;
            d[1] = z; d[2] = z; d[3] = z;
        }
    }
    __syncthreads();

    // ---- GEMM1: qkv = x_aug(64x208) @ W_aug^T (bias+scale folded).
    //      warp owns 3 gnt tiles x 4 mt; 13 kt steps of 16 ----
    {
        FragCF acc[3][4];
#pragma unroll
        for (int i = 0; i < 3; ++i)
#pragma unroll
            for (int j = 0; j < 4; ++j) wmma::fill_fragment(acc[i][j], 0.0f);

        const int gnt0 = wid * 3;
        for (int kt = 0; kt < 13; ++kt) {
            FragA af[4];
#pragma unroll
            for (int j = 0; j < 4; ++j)
                wmma::load_matrix_sync(af[j], scr + j * 16 * XS_LD + kt * 16, XS_LD);
#pragma unroll
            for (int i = 0; i < 3; ++i) {
                FragBR bf;
                wmma::load_matrix_sync(bf, g_qkvw_packed + ((gnt0 + i) * 13 + kt) * 256, 16);
#pragma unroll
                for (int j = 0; j < 4; ++j)
                    wmma::mma_sync(acc[i][j], af[j], bf, acc[i][j]);
            }
        }
#pragma unroll
        for (int i = 0; i < 3; ++i) {
            int gnt = gnt0 + i;
            int h   = gnt / 6;
            int ntl = gnt % 6;
            int col = (ntl >> 1) * 192 + h * 32 + (ntl & 1) * 16;
#pragma unroll
            for (int j = 0; j < 4; ++j)
                store_acc_half(qkvs + j * 16 * QK_LD + col, QK_LD, acc[i][j]);
        }
    }
    __syncthreads();

    // ================= attention middle: barrier-free =================
    // warp wid -> (mt = wid&3, hset = wid>>2), heads {hset, hset+3}; probs warp-private.
    {
        const int mt   = wid & 3;
        const int hset = wid >> 2;
        __half* probs = scr + wid * (16 * PR_LD);

#pragma unroll
        for (int hh = 0; hh < 2; ++hh) {
            const int h  = hset + 3 * hh;
            const int qo = h * 32;
            const int ko = 192 + h * 32;
            const int vo = 384 + h * 32;

            // ---- logits stripe: 16x64, K=32 (2 kt), bias preloaded (fp32 global) ----
            {
                FragCF acc[4];
#pragma unroll
                for (int nt = 0; nt < 4; ++nt)
                    wmma::load_matrix_sync(acc[nt],
                        bias + (size_t)h * 4096 + mt * 16 * 64 + nt * 16, 64,
                        wmma::mem_row_major);
#pragma unroll
                for (int kt = 0; kt < 2; ++kt) {
                    FragA af;
                    wmma::load_matrix_sync(af, qkvs + mt * 16 * QK_LD + qo + kt * 16, QK_LD);
#pragma unroll
                    for (int nt = 0; nt < 4; ++nt) {
                        FragBC bf;
                        wmma::load_matrix_sync(bf, qkvs + nt * 16 * QK_LD + ko + kt * 16, QK_LD);
                        wmma::mma_sync(acc[nt], af, bf, acc[nt]);
                    }
                }
#pragma unroll
                for (int nt = 0; nt < 4; ++nt)
                    store_acc_half(probs + nt * 16, PR_LD, acc[nt]);
            }
            __syncwarp();

            // ---- softmax on own stripe: 16 rows, 2 lanes/row x 32 cols ----
            {
                int r    = lane >> 1;
                int hf   = lane & 1;
                __half2* row = (__half2*)(probs + r * PR_LD + hf * 32);
                float vals[32];
                float mx = -1e30f;
#pragma unroll
                for (int i = 0; i < 16; ++i) {
                    float2 v = __half22float2(row[i]);
                    vals[2*i]   = v.x;
                    vals[2*i+1] = v.y;
                    mx = fmaxf(mx, fmaxf(v.x, v.y));
                }
                mx = fmaxf(mx, __shfl_xor_sync(0xffffffffu, mx, 1));
                float s = 0.0f;
#pragma unroll
                for (int i = 0; i < 32; ++i) {
                    float e = __expf(vals[i] - mx);
                    vals[i] = e;
                    s += e;
                }
                s += __shfl_xor_sync(0xffffffffu, s, 1);
                float inv = 1.0f / s;
#pragma unroll
                for (int i = 0; i < 16; ++i)
                    row[i] = __floats2half2_rn(vals[2*i] * inv, vals[2*i+1] * inv);
            }
            __syncwarp();

            // ---- AV stripe: probs(16x64) @ v(64x32), K=64 (4 kt) -> q-region ----
            {
                FragCF acc[2];
#pragma unroll
                for (int nt = 0; nt < 2; ++nt) wmma::fill_fragment(acc[nt], 0.0f);
#pragma unroll
                for (int kt = 0; kt < 4; ++kt) {
                    FragA af;
                    wmma::load_matrix_sync(af, probs + kt * 16, PR_LD);
#pragma unroll
                    for (int nt = 0; nt < 2; ++nt) {
                        FragBR bf;
                        wmma::load_matrix_sync(bf, qkvs + kt * 16 * QK_LD + vo + nt * 16, QK_LD);
                        wmma::mma_sync(acc[nt], af, bf, acc[nt]);
                    }
                }
#pragma unroll
                for (int nt = 0; nt < 2; ++nt)
                    store_acc_half(qkvs + mt * 16 * QK_LD + qo + nt * 16, QK_LD, acc[nt]);
            }
            __syncwarp();   // probs stripe reused by next head
        }
    }
    __syncthreads();

    // ---- proj: float out = attn_out(64x192 half) @ proj_w^T, K=192 (12 kt).
    //      float output overlaid on dead k/v half-region (float cols 96..287) ----
    {
        FragCF acc[4];
#pragma unroll
        for (int j = 0; j < 4; ++j) wmma::fill_fragment(acc[j], 0.0f);
        for (int kt = 0; kt < 12; ++kt) {
            FragBR bf;
            wmma::load_matrix_sync(bf, g_projw_packed + (wid * 12 + kt) * 256, 16);
#pragma unroll
            for (int j = 0; j < 4; ++j) {
                FragA af;
                wmma::load_matrix_sync(af, qkvs + j * 16 * QK_LD + kt * 16, QK_LD);
                wmma::mma_sync(acc[j], af, bf, acc[j]);
            }
        }
        float* po = (float*)qkvs + 96 + wid * 16;   // float stride = QK_LD/2 = 292
#pragma unroll
        for (int j = 0; j < 4; ++j)
            wmma::store_matrix_sync(po + j * 16 * 292, acc[j], 292, wmma::mem_row_major);
    }
    __syncthreads();

    // ---- epilogue: add proj_b, scatter to (B, H*W, C) ----
    {
        float* ob = out + (size_t)b * 65536 * CCH;
        const float* pf = (const float*)qkvs + 96;
        for (int i = tid; i < 64 * 48; i += NTHREADS) {
            int r  = i / 48;
            int c4 = i % 48;
            float4 v  = *(const float4*)(pf + r * 292 + c4 * 4);
            float4 pb = *(const float4*)(proj_b + c4 * 4);
            v.x += pb.x; v.y += pb.y; v.z += pb.z; v.w += pb.w;
            int iy = wh * 8 + (r >> 3);
            int ix = ww * 8 + (r & 7);
            *(float4*)(ob + (size_t)(iy * 256 + ix) * CCH + c4 * 4) = v;
        }
    }
}

extern "C" void kernel_launch(void* const* d_in, const int* in_sizes, int n_in,
                              void* d_out, int out_size)
{
    const float* x      = (const float*)d_in[0];
    const float* qkv_w  = (const float*)d_in[1];
    const float* qkv_b  = (const float*)d_in[2];
    const float* proj_w = (const float*)d_in[3];
    const float* proj_b = (const float*)d_in[4];
    const float* bias   = (const float*)d_in[5];
    float* out = (float*)d_out;

    repack_kernel<<<(156672 + 255) / 256, 256>>>(qkv_w, qkv_b, proj_w);

    cudaFuncSetAttribute(win_attn_kernel,
                         cudaFuncAttributeMaxDynamicSharedMemorySize, SMEM_BYTES);
    win_attn_kernel<<<NWIN, NTHREADS, SMEM_BYTES>>>(x, proj_b, bias, out);
}

// round 9
// speedup vs baseline: 7.1201x; 1.1810x over previous
#include <cuda_runtime.h>
#include <cuda_fp16.h>
#include <mma.h>

using namespace nvcuda;

#define NWIN 4096       // 4 * 32 * 32 windows
#define CCH  192
#define NTHREADS 192    // 6 warps, 2 CTAs/SM

// all strides in HALF elements
#define XS_LD  216      // x augmented to 208 cols (192 + 16 aug) + pad
#define QK_LD  584      // qkv 576 cols + pad; float view stride = 292
#define PR_LD  72       // per-warp probs stripe: 16 rows x 72

#define SCR_HALFS (64 * XS_LD)             // 13824 >= 6 * 16 * PR_LD
#define SMEM_HALFS (64 * QK_LD + SCR_HALFS)
#define SMEM_BYTES (SMEM_HALFS * 2)        // 102400 B -> 2 CTAs/SM

// packed qkv weights as half, fragment-ready [16k][16n] tiles:
// [gnt(36)][kt(13)][256]; bias row at k==192 (scale folded into q)
__device__ __half g_qkvw_packed[36 * 13 * 256];
// packed proj weights: [nt(12)][kt(12)][256]
__device__ __half g_projw_packed[12 * 12 * 256];
// bias repacked in fp32-accumulator fragment layout: [h*16 + mt*4 + nt][lane*8 + e]
__device__ float g_bias_packed[96 * 256];

__global__ void repack_kernel(const float* __restrict__ qkv_w,
                              const float* __restrict__ qkv_b,
                              const float* __restrict__ proj_w)
{
    int i = blockIdx.x * blockDim.x + threadIdx.x;
    const int NQ = 36 * 13 * 256;          // 119808
    const float scale = 0.17677669529663687f; // 1/sqrt(32)
    if (i < NQ) {
        int c  = i & 15;              // n col
        int r  = (i >> 4) & 15;       // k row within tile
        int t  = i >> 8;              // gnt*13 + kt
        int kt  = t % 13;
        int gnt = t / 13;
        int h   = gnt / 6;
        int ntl = gnt % 6;
        int blk  = ntl >> 1;          // 0=q,1=k,2=v
        int wrow = blk * 192 + h * 32 + (ntl & 1) * 16 + c;
        int k    = kt * 16 + r;
        float v;
        if (k < 192)       v = qkv_w[wrow * CCH + k];
        else if (k == 192) v = qkv_b[wrow];          // bias row (aug col = 1)
        else               v = 0.0f;
        if (blk == 0) v *= scale;
        g_qkvw_packed[i] = __float2half(v);
    } else if (i < NQ + 12 * 12 * 256) {
        int j  = i - NQ;
        int c  = j & 15;
        int r  = (j >> 4) & 15;
        int t  = j >> 8;              // nt*12 + kt
        int kt = t % 12;
        int nt = t / 12;
        g_projw_packed[j] = __float2half(proj_w[(nt * 16 + c) * CCH + kt * 16 + r]);
    }
}

// repack bias into the native m16n16k16 fp32 accumulator fragment layout
// (layout-agnostic: store f.x[e] by (lane, e); main kernel reads the same way)
__global__ void repack_bias_kernel(const float* __restrict__ bias)
{
    int wg = blockIdx.x * (blockDim.x >> 5) + (threadIdx.x >> 5);
    if (wg >= 96) return;
    int h  = wg >> 4;
    int mt = (wg >> 2) & 3;
    int nt = wg & 3;
    wmma::fragment<wmma::accumulator,16,16,16,float> f;
    wmma::load_matrix_sync(f, bias + (size_t)h * 4096 + mt * 16 * 64 + nt * 16, 64,
                           wmma::mem_row_major);
    int lane = threadIdx.x & 31;
    float* dst = g_bias_packed + wg * 256 + lane * 8;
#pragma unroll
    for (int e = 0; e < 8; ++e) dst[e] = f.x[e];
}

using FragA   = wmma::fragment<wmma::matrix_a,16,16,16,__half,wmma::row_major>;
using FragBR  = wmma::fragment<wmma::matrix_b,16,16,16,__half,wmma::row_major>;
using FragBC  = wmma::fragment<wmma::matrix_b,16,16,16,__half,wmma::col_major>;
using FragCF  = wmma::fragment<wmma::accumulator,16,16,16,float>;
using FragCH  = wmma::fragment<wmma::accumulator,16,16,16,__half>;

// store a float accumulator to half memory (acc layouts match for m16n16k16)
__device__ __forceinline__ void store_acc_half(__half* ptr, int ld, const FragCF& f) {
    FragCH h;
#pragma unroll
    for (int e = 0; e < f.num_elements; ++e) h.x[e] = __float2half(f.x[e]);
    wmma::store_matrix_sync(ptr, h, ld, wmma::mem_row_major);
}

__global__ __launch_bounds__(NTHREADS, 2)
void win_attn_kernel(const float* __restrict__ x,
                     const float* __restrict__ proj_b,
                     float* __restrict__ out)
{
    extern __shared__ __half smem[];
    __half* qkvs = smem;                  // [64][QK_LD] q|k|v half; later float proj out overlay
    __half* scr  = smem + 64 * QK_LD;     // x window / 6 warp-private probs stripes

    const int tid  = threadIdx.x;
    const int wid  = tid >> 5;            // 0..5
    const int lane = tid & 31;

    const int w   = blockIdx.x;
    const int b   = w >> 10;
    const int rem = w & 1023;
    const int wh  = rem >> 5;
    const int ww  = rem & 31;

    // ---- load x window (64 x 192) as half + augmentation cols ----
    {
        const float* xb = x + (size_t)b * 65536 * CCH;
        for (int i = tid; i < 64 * 48; i += NTHREADS) {
            int r  = i / 48;
            int c4 = i % 48;
            int iy = wh * 8 + (r >> 3);
            int ix = ww * 8 + (r & 7);
            float4 v = *(const float4*)(xb + (size_t)(iy * 256 + ix) * CCH + c4 * 4);
            __half2* d = (__half2*)(scr + r * XS_LD + c4 * 4);
            d[0] = __floats2half2_rn(v.x, v.y);
            d[1] = __floats2half2_rn(v.z, v.w);
        }
        // aug cols 192..207: col 192 = 1.0, rest 0
        for (int i = tid; i < 64 * 2; i += NTHREADS) {
            int r  = i >> 1;
            int g  = i & 1;
            __half2* d = (__half2*)(scr + r * XS_LD + 192 + g * 8);
            __half2 z = __floats2half2_rn(0.0f, 0.0f);
            d[0] = (g == 0) ? __floats2half2_rn(1.0f, 0.0f) : z;
            d[1] = z; d[2] = z; d[3] = z;
        }
    }
    __syncthreads();

    // ---- GEMM1: qkv = x_aug(64x208) @ W_aug^T (bias+scale folded).
    //      6 warps, two passes of (3 gnt x 4 mt); 13 kt steps of 16 ----
#pragma unroll
    for (int pass = 0; pass < 2; ++pass) {
        FragCF acc[3][4];
#pragma unroll
        for (int i = 0; i < 3; ++i)
#pragma unroll
            for (int j = 0; j < 4; ++j) wmma::fill_fragment(acc[i][j], 0.0f);

        const int gnt0 = wid * 3 + pass * 18;
        for (int kt = 0; kt < 13; ++kt) {
            FragA af[4];
#pragma unroll
            for (int j = 0; j < 4; ++j)
                wmma::load_matrix_sync(af[j], scr + j * 16 * XS_LD + kt * 16, XS_LD);
#pragma unroll
            for (int i = 0; i < 3; ++i) {
                FragBR bf;
                wmma::load_matrix_sync(bf, g_qkvw_packed + ((gnt0 + i) * 13 + kt) * 256, 16);
#pragma unroll
                for (int j = 0; j < 4; ++j)
                    wmma::mma_sync(acc[i][j], af[j], bf, acc[i][j]);
            }
        }
#pragma unroll
        for (int i = 0; i < 3; ++i) {
            int gnt = gnt0 + i;
            int h   = gnt / 6;
            int ntl = gnt % 6;
            int col = (ntl >> 1) * 192 + h * 32 + (ntl & 1) * 16;
#pragma unroll
            for (int j = 0; j < 4; ++j)
                store_acc_half(qkvs + j * 16 * QK_LD + col, QK_LD, acc[i][j]);
        }
    }
    __syncthreads();

    // ================= attention middle: barrier-free =================
    // 12 stripe-tasks (mt 0..3 x hset 0..2), warp does tasks {wid, wid+6};
    // each task covers heads {hset, hset+3}. probs stripe is warp-private.
    {
        __half* probs = scr + wid * (16 * PR_LD);

#pragma unroll
        for (int task = 0; task < 2; ++task) {
            const int t    = wid + task * 6;
            const int mt   = t & 3;
            const int hset = t >> 2;

#pragma unroll
            for (int hh = 0; hh < 2; ++hh) {
                const int h  = hset + 3 * hh;
                const int qo = h * 32;
                const int ko = 192 + h * 32;
                const int vo = 384 + h * 32;

                // ---- logits stripe: 16x64, K=32 (2 kt), bias from packed frags ----
                {
                    FragCF acc[4];
                    const float* bp = g_bias_packed + (size_t)(h * 16 + mt * 4) * 256 + lane * 8;
#pragma unroll
                    for (int nt = 0; nt < 4; ++nt) {
                        float4 a0 = *(const float4*)(bp + nt * 256);
                        float4 a1 = *(const float4*)(bp + nt * 256 + 4);
                        acc[nt].x[0] = a0.x; acc[nt].x[1] = a0.y;
                        acc[nt].x[2] = a0.z; acc[nt].x[3] = a0.w;
                        acc[nt].x[4] = a1.x; acc[nt].x[5] = a1.y;
                        acc[nt].x[6] = a1.z; acc[nt].x[7] = a1.w;
                    }
#pragma unroll
                    for (int kt = 0; kt < 2; ++kt) {
                        FragA af;
                        wmma::load_matrix_sync(af, qkvs + mt * 16 * QK_LD + qo + kt * 16, QK_LD);
#pragma unroll
                        for (int nt = 0; nt < 4; ++nt) {
                            FragBC bf;
                            wmma::load_matrix_sync(bf, qkvs + nt * 16 * QK_LD + ko + kt * 16, QK_LD);
                            wmma::mma_sync(acc[nt], af, bf, acc[nt]);
                        }
                    }
#pragma unroll
                    for (int nt = 0; nt < 4; ++nt)
                        store_acc_half(probs + nt * 16, PR_LD, acc[nt]);
                }
                __syncwarp();

                // ---- softmax on own stripe: 16 rows, 2 lanes/row, uint4 I/O ----
                {
                    int r  = lane >> 1;
                    int hf = lane & 1;
                    uint4* row = (uint4*)(probs + r * PR_LD + hf * 32);
                    float vals[32];
                    float mx = -1e30f;
#pragma unroll
                    for (int i = 0; i < 4; ++i) {
                        uint4 u = row[i];
                        float2 f0 = __half22float2(*(__half2*)&u.x);
                        float2 f1 = __half22float2(*(__half2*)&u.y);
                        float2 f2 = __half22float2(*(__half2*)&u.z);
                        float2 f3 = __half22float2(*(__half2*)&u.w);
                        vals[i*8+0] = f0.x; vals[i*8+1] = f0.y;
                        vals[i*8+2] = f1.x; vals[i*8+3] = f1.y;
                        vals[i*8+4] = f2.x; vals[i*8+5] = f2.y;
                        vals[i*8+6] = f3.x; vals[i*8+7] = f3.y;
                        mx = fmaxf(mx, fmaxf(fmaxf(f0.x, f0.y), fmaxf(f1.x, f1.y)));
                        mx = fmaxf(mx, fmaxf(fmaxf(f2.x, f2.y), fmaxf(f3.x, f3.y)));
                    }
                    mx = fmaxf(mx, __shfl_xor_sync(0xffffffffu, mx, 1));
                    float s = 0.0f;
#pragma unroll
                    for (int i = 0; i < 32; ++i) {
                        float e = __expf(vals[i] - mx);
                        vals[i] = e;
                        s += e;
                    }
                    s += __shfl_xor_sync(0xffffffffu, s, 1);
                    float inv = 1.0f / s;
#pragma unroll
                    for (int i = 0; i < 4; ++i) {
                        uint4 u;
                        __half2 h0 = __floats2half2_rn(vals[i*8+0] * inv, vals[i*8+1] * inv);
                        __half2 h1 = __floats2half2_rn(vals[i*8+2] * inv, vals[i*8+3] * inv);
                        __half2 h2 = __floats2half2_rn(vals[i*8+4] * inv, vals[i*8+5] * inv);
                        __half2 h3 = __floats2half2_rn(vals[i*8+6] * inv, vals[i*8+7] * inv);
                        u.x = *(unsigned*)&h0; u.y = *(unsigned*)&h1;
                        u.z = *(unsigned*)&h2; u.w = *(unsigned*)&h3;
                        row[i] = u;
                    }
                }
                __syncwarp();

                // ---- AV stripe: probs(16x64) @ v(64x32), K=64 (4 kt) -> q-region ----
                {
                    FragCF acc[2];
#pragma unroll
                    for (int nt = 0; nt < 2; ++nt) wmma::fill_fragment(acc[nt], 0.0f);
#pragma unroll
                    for (int kt = 0; kt < 4; ++kt) {
                        FragA af;
                        wmma::load_matrix_sync(af, probs + kt * 16, PR_LD);
#pragma unroll
                        for (int nt = 0; nt < 2; ++nt) {
                            FragBR bf;
                            wmma::load_matrix_sync(bf, qkvs + kt * 16 * QK_LD + vo + nt * 16, QK_LD);
                            wmma::mma_sync(acc[nt], af, bf, acc[nt]);
                        }
                    }
#pragma unroll
                    for (int nt = 0; nt < 2; ++nt)
                        store_acc_half(qkvs + mt * 16 * QK_LD + qo + nt * 16, QK_LD, acc[nt]);
                }
                __syncwarp();   // probs stripe reused by next head
            }
        }
    }
    __syncthreads();

    // ---- proj: float out = attn_out(64x192 half) @ proj_w^T, K=192 (12 kt).
    //      warp owns nt {2w, 2w+1} x 4 mt; float out overlaid on dead k/v region ----
    {
        FragCF acc[2][4];
#pragma unroll
        for (int i = 0; i < 2; ++i)
#pragma unroll
            for (int j = 0; j < 4; ++j) wmma::fill_fragment(acc[i][j], 0.0f);

        for (int kt = 0; kt < 12; ++kt) {
            FragA af[4];
#pragma unroll
            for (int j = 0; j < 4; ++j)
                wmma::load_matrix_sync(af[j], qkvs + j * 16 * QK_LD + kt * 16, QK_LD);
#pragma unroll
            for (int i = 0; i < 2; ++i) {
                FragBR bf;
                wmma::load_matrix_sync(bf, g_projw_packed + ((2 * wid + i) * 12 + kt) * 256, 16);
#pragma unroll
                for (int j = 0; j < 4; ++j)
                    wmma::mma_sync(acc[i][j], af[j], bf, acc[i][j]);
            }
        }
        // float stride = QK_LD/2 = 292; float cols 96.. overlay the dead k/v half-region
#pragma unroll
        for (int i = 0; i < 2; ++i) {
            float* po = (float*)qkvs + 96 + (2 * wid + i) * 16;
#pragma unroll
            for (int j = 0; j < 4; ++j)
                wmma::store_matrix_sync(po + j * 16 * 292, acc[i][j], 292, wmma::mem_row_major);
        }
    }
    __syncthreads();

    // ---- epilogue: add proj_b, scatter to (B, H*W, C) ----
    {
        float* ob = out + (size_t)b * 65536 * CCH;
        const float* pf = (const float*)qkvs + 96;
        for (int i = tid; i < 64 * 48; i += NTHREADS) {
            int r  = i / 48;
            int c4 = i % 48;
            float4 v  = *(const float4*)(pf + r * 292 + c4 * 4);
            float4 pb = *(const float4*)(proj_b + c4 * 4);
            v.x += pb.x; v.y += pb.y; v.z += pb.z; v.w += pb.w;
            int iy = wh * 8 + (r >> 3);
            int ix = ww * 8 + (r & 7);
            *(float4*)(ob + (size_t)(iy * 256 + ix) * CCH + c4 * 4) = v;
        }
    }
}

extern "C" void kernel_launch(void* const* d_in, const int* in_sizes, int n_in,
                              void* d_out, int out_size)
{
    const float* x      = (const float*)d_in[0];
    const float* qkv_w  = (const float*)d_in[1];
    const float* qkv_b  = (const float*)d_in[2];
    const float* proj_w = (const float*)d_in[3];
    const float* proj_b = (const float*)d_in[4];
    const float* bias   = (const float*)d_in[5];
    float* out = (float*)d_out;

    repack_kernel<<<(156672 + 255) / 256, 256>>>(qkv_w, qkv_b, proj_w);
    repack_bias_kernel<<<12, 256>>>(bias);

    cudaFuncSetAttribute(win_attn_kernel,
                         cudaFuncAttributeMaxDynamicSharedMemorySize, SMEM_BYTES);
    win_attn_kernel<<<NWIN, NTHREADS, SMEM_BYTES>>>(x, proj_b, out);
}

// round 12
// speedup vs baseline: 7.3585x; 1.0335x over previous
#include <cuda_runtime.h>
#include <cuda_fp16.h>
#include <mma.h>

using namespace nvcuda;

#define NWIN 4096       // 4 * 32 * 32 windows
#define CCH  192
#define NTHREADS 192    // 6 warps, 2 CTAs/SM

// all strides in HALF elements
#define XS_LD  216      // x augmented to 208 cols (192 + 16 aug) + pad
#define QK_LD  584      // qkv 576 cols + pad; float view stride = 292

#define SCR_HALFS (64 * XS_LD)             // x staging
#define SMEM_HALFS (64 * QK_LD + SCR_HALFS)
#define SMEM_BYTES (SMEM_HALFS * 2)        // 102400 B -> 2 CTAs/SM

// packed qkv weights as half, fragment-ready [16k][16n] tiles:
// [gnt(36)][kt(13)][256]; bias row at k==192 (scale folded into q)
__device__ __half g_qkvw_packed[36 * 13 * 256];
// packed proj weights: [nt(12)][kt(12)][256]
__device__ __half g_projw_packed[12 * 12 * 256];
// bias in m16n8 fp32-accumulator per-lane layout:
// [h(6)][mt(4)][j(8 n8-blocks)][lane(32)][c(4)]  = 24576 floats
__device__ float g_bias2[6 * 4 * 8 * 128];

#define NQ_ELEMS (36 * 13 * 256)           // 119808
#define NP_ELEMS (12 * 12 * 256)           // 36864
#define NB_ELEMS (6 * 4 * 8 * 128)         // 24576
#define REPACK_TOTAL (NQ_ELEMS + NP_ELEMS + NB_ELEMS)   // 181248

__global__ void repack_kernel(const float* __restrict__ qkv_w,
                              const float* __restrict__ qkv_b,
                              const float* __restrict__ proj_w,
                              const float* __restrict__ bias)
{
    int i = blockIdx.x * blockDim.x + threadIdx.x;
    const float scale = 0.17677669529663687f; // 1/sqrt(32)
    if (i < NQ_ELEMS) {
        int c  = i & 15;              // n col
        int r  = (i >> 4) & 15;       // k row within tile
        int t  = i >> 8;              // gnt*13 + kt
        int kt  = t % 13;
        int gnt = t / 13;
        int h   = gnt / 6;
        int ntl = gnt % 6;
        int blk  = ntl >> 1;          // 0=q,1=k,2=v
        int wrow = blk * 192 + h * 32 + (ntl & 1) * 16 + c;
        int k    = kt * 16 + r;
        float v;
        if (k < 192)       v = qkv_w[wrow * CCH + k];
        else if (k == 192) v = qkv_b[wrow];          // bias row (aug col = 1)
        else               v = 0.0f;
        if (blk == 0) v *= scale;
        g_qkvw_packed[i] = __float2half(v);
    } else if (i < NQ_ELEMS + NP_ELEMS) {
        int j  = i - NQ_ELEMS;
        int c  = j & 15;
        int r  = (j >> 4) & 15;
        int t  = j >> 8;              // nt*12 + kt
        int kt = t % 12;
        int nt = t / 12;
        g_projw_packed[j] = __float2half(proj_w[(nt * 16 + c) * CCH + kt * 16 + r]);
    } else if (i < REPACK_TOTAL) {
        int j2 = i - NQ_ELEMS - NP_ELEMS;
        int c    = j2 & 3;
        int lane = (j2 >> 2) & 31;
        int t    = j2 >> 7;           // (h*4+mt)*8 + jblk
        int jblk = t & 7;
        int mt   = (t >> 3) & 3;
        int h    = t >> 5;
        int row  = mt * 16 + (lane >> 2) + ((c >= 2) ? 8 : 0);
        int col  = jblk * 8 + 2 * (lane & 3) + (c & 1);
        g_bias2[j2] = bias[(size_t)h * 4096 + row * 64 + col];
    }
}

using FragA   = wmma::fragment<wmma::matrix_a,16,16,16,__half,wmma::row_major>;
using FragBR  = wmma::fragment<wmma::matrix_b,16,16,16,__half,wmma::row_major>;
using FragCF  = wmma::fragment<wmma::accumulator,16,16,16,float>;
using FragCH  = wmma::fragment<wmma::accumulator,16,16,16,__half>;

// store a float accumulator to half memory (acc layouts match for m16n16k16)
__device__ __forceinline__ void store_acc_half(__half* ptr, int ld, const FragCF& f) {
    FragCH h;
#pragma unroll
    for (int e = 0; e < f.num_elements; ++e) h.x[e] = __float2half(f.x[e]);
    wmma::store_matrix_sync(ptr, h, ld, wmma::mem_row_major);
}

__device__ __forceinline__ void mma16816(float* d,
    unsigned a0, unsigned a1, unsigned a2, unsigned a3,
    unsigned b0, unsigned b1)
{
    asm volatile(
        "mma.sync.aligned.m16n8k16.row.col.f32.f16.f16.f32 "
        "{%0,%1,%2,%3}, {%4,%5,%6,%7}, {%8,%9}, {%0,%1,%2,%3};"
        : "+f"(d[0]), "+f"(d[1]), "+f"(d[2]), "+f"(d[3])
        : "r"(a0), "r"(a1), "r"(a2), "r"(a3), "r"(b0), "r"(b1));
}

__device__ __forceinline__ void ldsm_x4_trans(
    unsigned& r0, unsigned& r1, unsigned& r2, unsigned& r3, unsigned addr)
{
    asm volatile(
        "ldmatrix.sync.aligned.m8n8.x4.trans.shared.b16 {%0,%1,%2,%3}, [%4];"
        : "=r"(r0), "=r"(r1), "=r"(r2), "=r"(r3) : "r"(addr));
}

__global__ __launch_bounds__(NTHREADS, 2)
void win_attn_kernel(const float* __restrict__ x,
                     const float* __restrict__ proj_b,
                     float* __restrict__ out)
{
    extern __shared__ __half smem[];
    __half* qkvs = smem;                  // [64][QK_LD] q|k|v half; later float proj out overlay
    __half* scr  = smem + 64 * QK_LD;     // x window staging

    const int tid  = threadIdx.x;
    const int wid  = tid >> 5;            // 0..5
    const int lane = tid & 31;
    const int r4   = lane >> 2;           // 0..7
    const int lt   = lane & 3;            // 0..3

    const int w   = blockIdx.x;
    const int b   = w >> 10;
    const int rem = w & 1023;
    const int wh  = rem >> 5;
    const int ww  = rem & 31;

    // ---- load x window (64 x 192) as half + augmentation cols ----
    {
        const float* xb = x + (size_t)b * 65536 * CCH;
        for (int i = tid; i < 64 * 48; i += NTHREADS) {
            int r  = i / 48;
            int c4 = i % 48;
            int iy = wh * 8 + (r >> 3);
            int ix = ww * 8 + (r & 7);
            float4 v = *(const float4*)(xb + (size_t)(iy * 256 + ix) * CCH + c4 * 4);
            __half2* d = (__half2*)(scr + r * XS_LD + c4 * 4);
            d[0] = __floats2half2_rn(v.x, v.y);
            d[1] = __floats2half2_rn(v.z, v.w);
        }
        // aug cols 192..207: col 192 = 1.0, rest 0
        for (int i = tid; i < 64 * 2; i += NTHREADS) {
            int r  = i >> 1;
            int g  = i & 1;
            __half2* d = (__half2*)(scr + r * XS_LD + 192 + g * 8);
            __half2 z = __floats2half2_rn(0.0f, 0.0f);
            d[0] = (g == 0) ? __floats2half2_rn(1.0f, 0.0f) : z;
            d[1] = z; d[2] = z; d[3] = z;
        }
    }
    __syncthreads();

    // ---- GEMM1: qkv = x_aug(64x208) @ W_aug^T (bias+scale folded).
    //      6 warps, two passes of (3 gnt x 4 mt); 13 kt steps of 16 ----
#pragma unroll
    for (int pass = 0; pass < 2; ++pass) {
        FragCF acc[3][4];
#pragma unroll
        for (int i = 0; i < 3; ++i)
#pragma unroll
            for (int j = 0; j < 4; ++j) wmma::fill_fragment(acc[i][j], 0.0f);

        const int gnt0 = wid * 3 + pass * 18;
        for (int kt = 0; kt < 13; ++kt) {
            FragA af[4];
#pragma unroll
            for (int j = 0; j < 4; ++j)
                wmma::load_matrix_sync(af[j], scr + j * 16 * XS_LD + kt * 16, XS_LD);
#pragma unroll
            for (int i = 0; i < 3; ++i) {
                FragBR bf;
                wmma::load_matrix_sync(bf, g_qkvw_packed + ((gnt0 + i) * 13 + kt) * 256, 16);
#pragma unroll
                for (int j = 0; j < 4; ++j)
                    wmma::mma_sync(acc[i][j], af[j], bf, acc[i][j]);
            }
        }
#pragma unroll
        for (int i = 0; i < 3; ++i) {
            int gnt = gnt0 + i;
            int h   = gnt / 6;
            int ntl = gnt % 6;
            int col = (ntl >> 1) * 192 + h * 32 + (ntl & 1) * 16;
#pragma unroll
            for (int j = 0; j < 4; ++j)
                store_acc_half(qkvs + j * 16 * QK_LD + col, QK_LD, acc[i][j]);
        }
    }
    __syncthreads();

    // ================= attention middle: register-resident (FA-style) =================
    // 12 stripe-tasks (mt 0..3 x hset 0..2), warp does {wid, wid+6};
    // each task covers heads {hset, hset+3}. S and P never touch smem.
    {
#pragma unroll
        for (int task = 0; task < 2; ++task) {
            const int t0   = wid + task * 6;
            const int mt   = t0 & 3;
            const int hset = t0 >> 2;

#pragma unroll
            for (int hh = 0; hh < 2; ++hh) {
                const int h  = hset + 3 * hh;
                const int qo = h * 32;
                const int ko = 192 + h * 32;
                const int vo = 384 + h * 32;

                // ---- logits in registers: S[8 blocks][4], init from packed bias ----
                float s[8][4];
                {
                    const float* bp = g_bias2 + (size_t)((h * 4 + mt) * 8) * 128 + lane * 4;
#pragma unroll
                    for (int j = 0; j < 8; ++j) {
                        float4 bb = *(const float4*)(bp + j * 128);
                        s[j][0] = bb.x; s[j][1] = bb.y; s[j][2] = bb.z; s[j][3] = bb.w;
                    }
#pragma unroll
                    for (int kc = 0; kc < 2; ++kc) {
                        const __half* qp = qkvs + (mt * 16 + r4) * QK_LD + qo + kc * 16 + 2 * lt;
                        unsigned a0 = *(const unsigned*)(qp);
                        unsigned a1 = *(const unsigned*)(qp + 8 * QK_LD);
                        unsigned a2 = *(const unsigned*)(qp + 8);
                        unsigned a3 = *(const unsigned*)(qp + 8 * QK_LD + 8);
#pragma unroll
                        for (int j = 0; j < 8; ++j) {
                            const __half* kp = qkvs + (j * 8 + r4) * QK_LD + ko + kc * 16 + 2 * lt;
                            unsigned b0 = *(const unsigned*)(kp);
                            unsigned b1 = *(const unsigned*)(kp + 8);
                            mma16816(s[j], a0, a1, a2, a3, b0, b1);
                        }
                    }
                }

                // ---- softmax in registers: rows r4 (c0,c1) and r4+8 (c2,c3) ----
                unsigned pa[8], pb[8];
                {
                    float mx0 = -1e30f, mx1 = -1e30f;
#pragma unroll
                    for (int j = 0; j < 8; ++j) {
                        mx0 = fmaxf(mx0, fmaxf(s[j][0], s[j][1]));
                        mx1 = fmaxf(mx1, fmaxf(s[j][2], s[j][3]));
                    }
                    mx0 = fmaxf(mx0, __shfl_xor_sync(0xffffffffu, mx0, 1));
                    mx0 = fmaxf(mx0, __shfl_xor_sync(0xffffffffu, mx0, 2));
                    mx1 = fmaxf(mx1, __shfl_xor_sync(0xffffffffu, mx1, 1));
                    mx1 = fmaxf(mx1, __shfl_xor_sync(0xffffffffu, mx1, 2));
                    float s0 = 0.0f, s1 = 0.0f;
#pragma unroll
                    for (int j = 0; j < 8; ++j) {
                        s[j][0] = __expf(s[j][0] - mx0);
                        s[j][1] = __expf(s[j][1] - mx0);
                        s[j][2] = __expf(s[j][2] - mx1);
                        s[j][3] = __expf(s[j][3] - mx1);
                        s0 += s[j][0] + s[j][1];
                        s1 += s[j][2] + s[j][3];
                    }
                    s0 += __shfl_xor_sync(0xffffffffu, s0, 1);
                    s0 += __shfl_xor_sync(0xffffffffu, s0, 2);
                    s1 += __shfl_xor_sync(0xffffffffu, s1, 1);
                    s1 += __shfl_xor_sync(0xffffffffu, s1, 2);
                    float i0 = 1.0f / s0, i1 = 1.0f / s1;
#pragma unroll
                    for (int j = 0; j < 8; ++j) {
                        __half2 lo = __floats2half2_rn(s[j][0] * i0, s[j][1] * i0);
                        __half2 hi = __floats2half2_rn(s[j][2] * i1, s[j][3] * i1);
                        pa[j] = *(unsigned*)&lo;
                        pb[j] = *(unsigned*)&hi;
                    }
                }

                // ---- AV: O(16x32) = P(16x64) @ V(64x32); P from regs, V via ldmatrix.trans ----
                {
                    float o[4][4];
#pragma unroll
                    for (int jn = 0; jn < 4; ++jn)
#pragma unroll
                        for (int c = 0; c < 4; ++c) o[jn][c] = 0.0f;

#pragma unroll
                    for (int kc = 0; kc < 4; ++kc) {
                        unsigned a0 = pa[2 * kc],     a1 = pb[2 * kc];
                        unsigned a2 = pa[2 * kc + 1], a3 = pb[2 * kc + 1];
#pragma unroll
                        for (int nbh = 0; nbh < 2; ++nbh) {
                            const __half* vp = qkvs + (kc * 16 + (lane & 15)) * QK_LD
                                             + vo + nbh * 16 + (lane >> 4) * 8;
                            unsigned addr = (unsigned)__cvta_generic_to_shared(vp);
                            unsigned v0, v1, v2, v3;
                            ldsm_x4_trans(v0, v1, v2, v3, addr);
                            mma16816(o[nbh * 2 + 0], a0, a1, a2, a3, v0, v1);
                            mma16816(o[nbh * 2 + 1], a0, a1, a2, a3, v2, v3);
                        }
                    }
                    // store O to q-region (dead): rows mt*16 + r4 (+8), cols qo + jn*8 + 2*lt
                    __half* op = qkvs + (mt * 16 + r4) * QK_LD + qo + 2 * lt;
#pragma unroll
                    for (int jn = 0; jn < 4; ++jn) {
                        __half2 lo = __floats2half2_rn(o[jn][0], o[jn][1]);
                        __half2 hi = __floats2half2_rn(o[jn][2], o[jn][3]);
                        *(unsigned*)(op + jn * 8)               = *(unsigned*)&lo;
                        *(unsigned*)(op + jn * 8 + 8 * QK_LD)   = *(unsigned*)&hi;
                    }
                }
            }
        }
    }
    __syncthreads();

    // ---- proj: float out = attn_out(64x192 half) @ proj_w^T, K=192 (12 kt).
    //      warp owns nt {2w, 2w+1} x 4 mt; float out overlaid on dead k/v region ----
    {
        FragCF acc[2][4];
#pragma unroll
        for (int i = 0; i < 2; ++i)
#pragma unroll
            for (int j = 0; j < 4; ++j) wmma::fill_fragment(acc[i][j], 0.0f);

        for (int kt = 0; kt < 12; ++kt) {
            FragA af[4];
#pragma unroll
            for (int j = 0; j < 4; ++j)
                wmma::load_matrix_sync(af[j], qkvs + j * 16 * QK_LD + kt * 16, QK_LD);
#pragma unroll
            for (int i = 0; i < 2; ++i) {
                FragBR bf;
                wmma::load_matrix_sync(bf, g_projw_packed + ((2 * wid + i) * 12 + kt) * 256, 16);
#pragma unroll
                for (int j = 0; j < 4; ++j)
                    wmma::mma_sync(acc[i][j], af[j], bf, acc[i][j]);
            }
        }
        // float stride = QK_LD/2 = 292; float cols 96.. overlay the dead k/v half-region
#pragma unroll
        for (int i = 0; i < 2; ++i) {
            float* po = (float*)qkvs + 96 + (2 * wid + i) * 16;
#pragma unroll
            for (int j = 0; j < 4; ++j)
                wmma::store_matrix_sync(po + j * 16 * 292, acc[i][j], 292, wmma::mem_row_major);
        }
    }
    __syncthreads();

    // ---- epilogue: add proj_b, scatter to (B, H*W, C) ----
    {
        float* ob = out + (size_t)b * 65536 * CCH;
        const float* pf = (const float*)qkvs + 96;
        for (int i = tid; i < 64 * 48; i += NTHREADS) {
            int r  = i / 48;
            int c4 = i % 48;
            float4 v  = *(const float4*)(pf + r * 292 + c4 * 4);
            float4 pb = *(const float4*)(proj_b + c4 * 4);
            v.x += pb.x; v.y += pb.y; v.z += pb.z; v.w += pb.w;
            int iy = wh * 8 + (r >> 3);
            int ix = ww * 8 + (r & 7);
            *(float4*)(ob + (size_t)(iy * 256 + ix) * CCH + c4 * 4) = v;
        }
    }
}

extern "C" void kernel_launch(void* const* d_in, const int* in_sizes, int n_in,
                              void* d_out, int out_size)
{
    const float* x      = (const float*)d_in[0];
    const float* qkv_w  = (const float*)d_in[1];
    const float* qkv_b  = (const float*)d_in[2];
    const float* proj_w = (const float*)d_in[3];
    const float* proj_b = (const float*)d_in[4];
    const float* bias   = (const float*)d_in[5];
    float* out = (float*)d_out;

    // 119808 + 36864 + 24576 = 181248 elements to repack (bias table FULLY covered)
    repack_kernel<<<(REPACK_TOTAL + 255) / 256, 256>>>(qkv_w, qkv_b, proj_w, bias);

    cudaFuncSetAttribute(win_attn_kernel,
                         cudaFuncAttributeMaxDynamicSharedMemorySize, SMEM_BYTES);
    win_attn_kernel<<<NWIN, NTHREADS, SMEM_BYTES>>>(x, proj_b, out);
}

// round 13
// speedup vs baseline: 7.3761x; 1.0024x over previous
#include <cuda_runtime.h>
#include <cuda_fp16.h>
#include <mma.h>

using namespace nvcuda;

#define NWIN 4096       // 4 * 32 * 32 windows
#define CCH  192
#define NTHREADS 192    // 6 warps, 2 CTAs/SM

// all strides in HALF elements
#define XS_LD  216      // x augmented to 208 cols (192 + 16 aug) + pad
#define QK_LD  584      // qkv 576 cols + pad; float view stride = 292

#define SCR_HALFS (64 * XS_LD)             // x staging
#define SMEM_HALFS (64 * QK_LD + SCR_HALFS)
#define SMEM_BYTES (SMEM_HALFS * 2)        // 102400 B -> 2 CTAs/SM

// packed qkv weights as half, fragment-ready [16k][16n] tiles:
// [gnt(36)][kt(13)][256]; bias row at k==192 (scale folded into q)
__device__ __half g_qkvw_packed[36 * 13 * 256];
// packed proj weights: [nt(12)][kt(12)][256]
__device__ __half g_projw_packed[12 * 12 * 256];
// bias in m16n8 fp32-accumulator per-lane layout, stored as HALF:
// [h(6)][mt(4)][j(8 n8-blocks)][lane(32)][c(4)]  = 24576 halves
__device__ __half g_bias2h[6 * 4 * 8 * 128];

#define NQ_ELEMS (36 * 13 * 256)           // 119808
#define NP_ELEMS (12 * 12 * 256)           // 36864
#define NB_ELEMS (6 * 4 * 8 * 128)         // 24576
#define REPACK_TOTAL (NQ_ELEMS + NP_ELEMS + NB_ELEMS)   // 181248

__global__ void repack_kernel(const float* __restrict__ qkv_w,
                              const float* __restrict__ qkv_b,
                              const float* __restrict__ proj_w,
                              const float* __restrict__ bias)
{
    int i = blockIdx.x * blockDim.x + threadIdx.x;
    const float scale = 0.17677669529663687f; // 1/sqrt(32)
    if (i < NQ_ELEMS) {
        int c  = i & 15;              // n col
        int r  = (i >> 4) & 15;       // k row within tile
        int t  = i >> 8;              // gnt*13 + kt
        int kt  = t % 13;
        int gnt = t / 13;
        int h   = gnt / 6;
        int ntl = gnt % 6;
        int blk  = ntl >> 1;          // 0=q,1=k,2=v
        int wrow = blk * 192 + h * 32 + (ntl & 1) * 16 + c;
        int k    = kt * 16 + r;
        float v;
        if (k < 192)       v = qkv_w[wrow * CCH + k];
        else if (k == 192) v = qkv_b[wrow];          // bias row (aug col = 1)
        else               v = 0.0f;
        if (blk == 0) v *= scale;
        g_qkvw_packed[i] = __float2half(v);
    } else if (i < NQ_ELEMS + NP_ELEMS) {
        int j  = i - NQ_ELEMS;
        int c  = j & 15;
        int r  = (j >> 4) & 15;
        int t  = j >> 8;              // nt*12 + kt
        int kt = t % 12;
        int nt = t / 12;
        g_projw_packed[j] = __float2half(proj_w[(nt * 16 + c) * CCH + kt * 16 + r]);
    } else if (i < REPACK_TOTAL) {
        int j2 = i - NQ_ELEMS - NP_ELEMS;
        int c    = j2 & 3;
        int lane = (j2 >> 2) & 31;
        int t    = j2 >> 7;           // (h*4+mt)*8 + jblk
        int jblk = t & 7;
        int mt   = (t >> 3) & 3;
        int h    = t >> 5;
        int row  = mt * 16 + (lane >> 2) + ((c >= 2) ? 8 : 0);
        int col  = jblk * 8 + 2 * (lane & 3) + (c & 1);
        g_bias2h[j2] = __float2half(bias[(size_t)h * 4096 + row * 64 + col]);
    }
}

using FragA   = wmma::fragment<wmma::matrix_a,16,16,16,__half,wmma::row_major>;
using FragBR  = wmma::fragment<wmma::matrix_b,16,16,16,__half,wmma::row_major>;
using FragCF  = wmma::fragment<wmma::accumulator,16,16,16,float>;
using FragCH  = wmma::fragment<wmma::accumulator,16,16,16,__half>;

// store a float accumulator to half memory (acc layouts match for m16n16k16)
__device__ __forceinline__ void store_acc_half(__half* ptr, int ld, const FragCF& f) {
    FragCH h;
#pragma unroll
    for (int e = 0; e < f.num_elements; ++e) h.x[e] = __float2half(f.x[e]);
    wmma::store_matrix_sync(ptr, h, ld, wmma::mem_row_major);
}

__device__ __forceinline__ void mma16816(float* d,
    unsigned a0, unsigned a1, unsigned a2, unsigned a3,
    unsigned b0, unsigned b1)
{
    asm volatile(
        "mma.sync.aligned.m16n8k16.row.col.f32.f16.f16.f32 "
        "{%0,%1,%2,%3}, {%4,%5,%6,%7}, {%8,%9}, {%0,%1,%2,%3};"
        : "+f"(d[0]), "+f"(d[1]), "+f"(d[2]), "+f"(d[3])
        : "r"(a0), "r"(a1), "r"(a2), "r"(a3), "r"(b0), "r"(b1));
}

__device__ __forceinline__ void ldsm_x4(
    unsigned& r0, unsigned& r1, unsigned& r2, unsigned& r3, unsigned addr)
{
    asm volatile(
        "ldmatrix.sync.aligned.m8n8.x4.shared.b16 {%0,%1,%2,%3}, [%4];"
        : "=r"(r0), "=r"(r1), "=r"(r2), "=r"(r3) : "r"(addr));
}

__device__ __forceinline__ void ldsm_x4_trans(
    unsigned& r0, unsigned& r1, unsigned& r2, unsigned& r3, unsigned addr)
{
    asm volatile(
        "ldmatrix.sync.aligned.m8n8.x4.trans.shared.b16 {%0,%1,%2,%3}, [%4];"
        : "=r"(r0), "=r"(r1), "=r"(r2), "=r"(r3) : "r"(addr));
}

__global__ __launch_bounds__(NTHREADS, 2)
void win_attn_kernel(const float* __restrict__ x,
                     const float* __restrict__ proj_b,
                     float* __restrict__ out)
{
    extern __shared__ __half smem[];
    __half* qkvs = smem;                  // [64][QK_LD] q|k|v half; later float proj out overlay
    __half* scr  = smem + 64 * QK_LD;     // x window staging

    const int tid  = threadIdx.x;
    const int wid  = tid >> 5;            // 0..5
    const int lane = tid & 31;
    const int r4   = lane >> 2;           // 0..7
    const int lt   = lane & 3;            // 0..3

    const int w   = blockIdx.x;
    const int b   = w >> 10;
    const int rem = w & 1023;
    const int wh  = rem >> 5;
    const int ww  = rem & 31;

    // ---- load x window (64 x 192) as half + augmentation cols ----
    {
        const float* xb = x + (size_t)b * 65536 * CCH;
        for (int i = tid; i < 64 * 48; i += NTHREADS) {
            int r  = i / 48;
            int c4 = i % 48;
            int iy = wh * 8 + (r >> 3);
            int ix = ww * 8 + (r & 7);
            float4 v = *(const float4*)(xb + (size_t)(iy * 256 + ix) * CCH + c4 * 4);
            __half2* d = (__half2*)(scr + r * XS_LD + c4 * 4);
            d[0] = __floats2half2_rn(v.x, v.y);
            d[1] = __floats2half2_rn(v.z, v.w);
        }
        // aug cols 192..207: col 192 = 1.0, rest 0
        for (int i = tid; i < 64 * 2; i += NTHREADS) {
            int r  = i >> 1;
            int g  = i & 1;
            __half2* d = (__half2*)(scr + r * XS_LD + 192 + g * 8);
            __half2 z = __floats2half2_rn(0.0f, 0.0f);
            d[0] = (g == 0) ? __floats2half2_rn(1.0f, 0.0f) : z;
            d[1] = z; d[2] = z; d[3] = z;
        }
    }
    __syncthreads();

    // ---- GEMM1: qkv = x_aug(64x208) @ W_aug^T (bias+scale folded).
    //      6 warps, two passes of (3 gnt x 4 mt); 13 kt steps of 16 ----
#pragma unroll
    for (int pass = 0; pass < 2; ++pass) {
        FragCF acc[3][4];
#pragma unroll
        for (int i = 0; i < 3; ++i)
#pragma unroll
            for (int j = 0; j < 4; ++j) wmma::fill_fragment(acc[i][j], 0.0f);

        const int gnt0 = wid * 3 + pass * 18;
        for (int kt = 0; kt < 13; ++kt) {
            FragA af[4];
#pragma unroll
            for (int j = 0; j < 4; ++j)
                wmma::load_matrix_sync(af[j], scr + j * 16 * XS_LD + kt * 16, XS_LD);
#pragma unroll
            for (int i = 0; i < 3; ++i) {
                FragBR bf;
                wmma::load_matrix_sync(bf, g_qkvw_packed + ((gnt0 + i) * 13 + kt) * 256, 16);
#pragma unroll
                for (int j = 0; j < 4; ++j)
                    wmma::mma_sync(acc[i][j], af[j], bf, acc[i][j]);
            }
        }
#pragma unroll
        for (int i = 0; i < 3; ++i) {
            int gnt = gnt0 + i;
            int h   = gnt / 6;
            int ntl = gnt % 6;
            int col = (ntl >> 1) * 192 + h * 32 + (ntl & 1) * 16;
#pragma unroll
            for (int j = 0; j < 4; ++j)
                store_acc_half(qkvs + j * 16 * QK_LD + col, QK_LD, acc[i][j]);
        }
    }
    __syncthreads();

    // ================= attention middle: warp = head, K/V register-hoisted =================
    // Warp h owns head h completely: K/V fragments loaded ONCE, reused across 4 mt stripes.
    // S and P never touch smem; O written to the warp-private q-column region.
    {
        const int h  = wid;
        const int qo = h * 32;
        const int ko = 192 + h * 32;
        const int vo = 384 + h * 32;

        // hoist K fragments: kb[kc][j][2]
        unsigned kb[2][8][2];
#pragma unroll
        for (int kc = 0; kc < 2; ++kc)
#pragma unroll
            for (int j = 0; j < 8; ++j) {
                const __half* kp = qkvs + (j * 8 + r4) * QK_LD + ko + kc * 16 + 2 * lt;
                kb[kc][j][0] = *(const unsigned*)(kp);
                kb[kc][j][1] = *(const unsigned*)(kp + 8);
            }

        // hoist V fragments via ldmatrix.trans: vb[kc][nbh][4]
        unsigned vb[4][2][4];
#pragma unroll
        for (int kc = 0; kc < 4; ++kc)
#pragma unroll
            for (int nbh = 0; nbh < 2; ++nbh) {
                const __half* vp = qkvs + (kc * 16 + (lane & 15)) * QK_LD
                                 + vo + nbh * 16 + (lane >> 4) * 8;
                unsigned addr = (unsigned)__cvta_generic_to_shared(vp);
                ldsm_x4_trans(vb[kc][nbh][0], vb[kc][nbh][1],
                              vb[kc][nbh][2], vb[kc][nbh][3], addr);
            }

#pragma unroll
        for (int mt = 0; mt < 4; ++mt) {
            // ---- logits in registers: S[8 blocks][4], init from half bias ----
            float s[8][4];
            {
                const __half* bp = g_bias2h + (size_t)((h * 4 + mt) * 8) * 128 + lane * 4;
#pragma unroll
                for (int j = 0; j < 8; ++j) {
                    uint2 u = *(const uint2*)(bp + j * 128);
                    float2 f0 = __half22float2(*(__half2*)&u.x);
                    float2 f1 = __half22float2(*(__half2*)&u.y);
                    s[j][0] = f0.x; s[j][1] = f0.y; s[j][2] = f1.x; s[j][3] = f1.y;
                }
                // Q via ldmatrix.x4 (non-trans): same addr pattern as V but q cols
#pragma unroll
                for (int kc = 0; kc < 2; ++kc) {
                    const __half* qp = qkvs + (mt * 16 + (lane & 15)) * QK_LD
                                     + qo + kc * 16 + (lane >> 4) * 8;
                    unsigned addr = (unsigned)__cvta_generic_to_shared(qp);
                    unsigned a0, a1, a2, a3;
                    ldsm_x4(a0, a1, a2, a3, addr);
#pragma unroll
                    for (int j = 0; j < 8; ++j)
                        mma16816(s[j], a0, a1, a2, a3, kb[kc][j][0], kb[kc][j][1]);
                }
            }

            // ---- softmax in registers: rows r4 (c0,c1) and r4+8 (c2,c3) ----
            unsigned pa[8], pb[8];
            {
                float mx0 = -1e30f, mx1 = -1e30f;
#pragma unroll
                for (int j = 0; j < 8; ++j) {
                    mx0 = fmaxf(mx0, fmaxf(s[j][0], s[j][1]));
                    mx1 = fmaxf(mx1, fmaxf(s[j][2], s[j][3]));
                }
                mx0 = fmaxf(mx0, __shfl_xor_sync(0xffffffffu, mx0, 1));
                mx0 = fmaxf(mx0, __shfl_xor_sync(0xffffffffu, mx0, 2));
                mx1 = fmaxf(mx1, __shfl_xor_sync(0xffffffffu, mx1, 1));
                mx1 = fmaxf(mx1, __shfl_xor_sync(0xffffffffu, mx1, 2));
                float s0 = 0.0f, s1 = 0.0f;
#pragma unroll
                for (int j = 0; j < 8; ++j) {
                    s[j][0] = __expf(s[j][0] - mx0);
                    s[j][1] = __expf(s[j][1] - mx0);
                    s[j][2] = __expf(s[j][2] - mx1);
                    s[j][3] = __expf(s[j][3] - mx1);
                    s0 += s[j][0] + s[j][1];
                    s1 += s[j][2] + s[j][3];
                }
                s0 += __shfl_xor_sync(0xffffffffu, s0, 1);
                s0 += __shfl_xor_sync(0xffffffffu, s0, 2);
                s1 += __shfl_xor_sync(0xffffffffu, s1, 1);
                s1 += __shfl_xor_sync(0xffffffffu, s1, 2);
                float i0 = 1.0f / s0, i1 = 1.0f / s1;
#pragma unroll
                for (int j = 0; j < 8; ++j) {
                    __half2 lo = __floats2half2_rn(s[j][0] * i0, s[j][1] * i0);
                    __half2 hi = __floats2half2_rn(s[j][2] * i1, s[j][3] * i1);
                    pa[j] = *(unsigned*)&lo;
                    pb[j] = *(unsigned*)&hi;
                }
            }

            // ---- AV: O(16x32) = P(16x64) @ V(64x32); all operands in registers ----
            {
                float o[4][4];
#pragma unroll
                for (int jn = 0; jn < 4; ++jn)
#pragma unroll
                    for (int c = 0; c < 4; ++c) o[jn][c] = 0.0f;

#pragma unroll
                for (int kc = 0; kc < 4; ++kc) {
                    unsigned a0 = pa[2 * kc],     a1 = pb[2 * kc];
                    unsigned a2 = pa[2 * kc + 1], a3 = pb[2 * kc + 1];
#pragma unroll
                    for (int nbh = 0; nbh < 2; ++nbh) {
                        mma16816(o[nbh * 2 + 0], a0, a1, a2, a3,
                                 vb[kc][nbh][0], vb[kc][nbh][1]);
                        mma16816(o[nbh * 2 + 1], a0, a1, a2, a3,
                                 vb[kc][nbh][2], vb[kc][nbh][3]);
                    }
                }
                // store O to q-region (dead): rows mt*16 + r4 (+8), cols qo + jn*8 + 2*lt
                __half* op = qkvs + (mt * 16 + r4) * QK_LD + qo + 2 * lt;
#pragma unroll
                for (int jn = 0; jn < 4; ++jn) {
                    __half2 lo = __floats2half2_rn(o[jn][0], o[jn][1]);
                    __half2 hi = __floats2half2_rn(o[jn][2], o[jn][3]);
                    *(unsigned*)(op + jn * 8)               = *(unsigned*)&lo;
                    *(unsigned*)(op + jn * 8 + 8 * QK_LD)   = *(unsigned*)&hi;
                }
            }
        }
    }
    __syncthreads();

    // ---- proj: float out = attn_out(64x192 half) @ proj_w^T, K=192 (12 kt).
    //      warp owns nt {2w, 2w+1} x 4 mt; float out overlaid on dead k/v region ----
    {
        FragCF acc[2][4];
#pragma unroll
        for (int i = 0; i < 2; ++i)
#pragma unroll
            for (int j = 0; j < 4; ++j) wmma::fill_fragment(acc[i][j], 0.0f);

        for (int kt = 0; kt < 12; ++kt) {
            FragA af[4];
#pragma unroll
            for (int j = 0; j < 4; ++j)
                wmma::load_matrix_sync(af[j], qkvs + j * 16 * QK_LD + kt * 16, QK_LD);
#pragma unroll
            for (int i = 0; i < 2; ++i) {
                FragBR bf;
                wmma::load_matrix_sync(bf, g_projw_packed + ((2 * wid + i) * 12 + kt) * 256, 16);
#pragma unroll
                for (int j = 0; j < 4; ++j)
                    wmma::mma_sync(acc[i][j], af[j], bf, acc[i][j]);
            }
        }
        // float stride = QK_LD/2 = 292; float cols 96.. overlay the dead k/v half-region
#pragma unroll
        for (int i = 0; i < 2; ++i) {
            float* po = (float*)qkvs + 96 + (2 * wid + i) * 16;
#pragma unroll
            for (int j = 0; j < 4; ++j)
                wmma::store_matrix_sync(po + j * 16 * 292, acc[i][j], 292, wmma::mem_row_major);
        }
    }
    __syncthreads();

    // ---- epilogue: add proj_b, scatter to (B, H*W, C) ----
    {
        float* ob = out + (size_t)b * 65536 * CCH;
        const float* pf = (const float*)qkvs + 96;
        for (int i = tid; i < 64 * 48; i += NTHREADS) {
            int r  = i / 48;
            int c4 = i % 48;
            float4 v  = *(const float4*)(pf + r * 292 + c4 * 4);
            float4 pb = *(const float4*)(proj_b + c4 * 4);
            v.x += pb.x; v.y += pb.y; v.z += pb.z; v.w += pb.w;
            int iy = wh * 8 + (r >> 3);
            int ix = ww * 8 + (r & 7);
            *(float4*)(ob + (size_t)(iy * 256 + ix) * CCH + c4 * 4) = v;
        }
    }
}

extern "C" void kernel_launch(void* const* d_in, const int* in_sizes, int n_in,
                              void* d_out, int out_size)
{
    const float* x      = (const float*)d_in[0];
    const float* qkv_w  = (const float*)d_in[1];
    const float* qkv_b  = (const float*)d_in[2];
    const float* proj_w = (const float*)d_in[3];
    const float* proj_b = (const float*)d_in[4];
    const float* bias   = (const float*)d_in[5];
    float* out = (float*)d_out;

    repack_kernel<<<(REPACK_TOTAL + 255) / 256, 256>>>(qkv_w, qkv_b, proj_w, bias);

    cudaFuncSetAttribute(win_attn_kernel,
                         cudaFuncAttributeMaxDynamicSharedMemorySize, SMEM_BYTES);
    win_attn_kernel<<<NWIN, NTHREADS, SMEM_BYTES>>>(x, proj_b, out);
}

// round 14
// speedup vs baseline: 8.1411x; 1.1037x over previous
#include <cuda_runtime.h>
#include <cuda_fp16.h>
#include <mma.h>

using namespace nvcuda;

#define NWIN 4096       // 4 * 32 * 32 windows
#define CCH  192
#define NTHREADS 192    // 6 warps, 2 CTAs/SM

// all strides in HALF elements
#define XS_LD  216      // x augmented to 208 cols (192 + 16 aug) + pad
#define QK_LD  592      // qkv 576 cols + pad; word stride 296 (== 8 mod 32 -> uniform 2-way)

#define SCR_HALFS (64 * XS_LD)             // x staging
#define SMEM_HALFS (64 * QK_LD + SCR_HALFS)
#define SMEM_BYTES (SMEM_HALFS * 2)        // 103424 B -> 2 CTAs/SM

// packed qkv weights as half, fragment-ready [16k][16n] tiles:
// [gnt(36)][kt(13)][256]; bias row at k==192 (scale folded into q)
__device__ __half g_qkvw_packed[36 * 13 * 256];
// proj weights in raw m16n8k16 B-operand per-lane layout:
// [nb(24 n8-blocks)][kt(12)][lane(32)][2 unsigned]  (b0 = k 2lt..; b1 = k+8)
__device__ unsigned g_projw2[24 * 12 * 64];
// bias in m16n8 fp32-accumulator per-lane layout, stored as HALF:
// [h(6)][mt(4)][j(8 n8-blocks)][lane(32)][c(4)]  = 24576 halves
__device__ __half g_bias2h[6 * 4 * 8 * 128];

#define NQ_ELEMS  (36 * 13 * 256)          // 119808
#define NP2_ELEMS (24 * 12 * 64)           // 18432 (unsigned)
#define NB_ELEMS  (6 * 4 * 8 * 128)        // 24576
#define REPACK_TOTAL (NQ_ELEMS + NP2_ELEMS + NB_ELEMS)   // 162816

__global__ void repack_kernel(const float* __restrict__ qkv_w,
                              const float* __restrict__ qkv_b,
                              const float* __restrict__ proj_w,
                              const float* __restrict__ bias)
{
    int i = blockIdx.x * blockDim.x + threadIdx.x;
    const float scale = 0.17677669529663687f; // 1/sqrt(32)
    if (i < NQ_ELEMS) {
        int c  = i & 15;              // n col
        int r  = (i >> 4) & 15;       // k row within tile
        int t  = i >> 8;              // gnt*13 + kt
        int kt  = t % 13;
        int gnt = t / 13;
        int h   = gnt / 6;
        int ntl = gnt % 6;
        int blk  = ntl >> 1;          // 0=q,1=k,2=v
        int wrow = blk * 192 + h * 32 + (ntl & 1) * 16 + c;
        int k    = kt * 16 + r;
        float v;
        if (k < 192)       v = qkv_w[wrow * CCH + k];
        else if (k == 192) v = qkv_b[wrow];          // bias row (aug col = 1)
        else               v = 0.0f;
        if (blk == 0) v *= scale;
        g_qkvw_packed[i] = __float2half(v);
    } else if (i < NQ_ELEMS + NP2_ELEMS) {
        int j  = i - NQ_ELEMS;        // unsigned index
        int u    = j & 1;
        int lane = (j >> 1) & 31;
        int t    = j >> 6;            // nb*12 + kt
        int kt = t % 12;
        int nb = t / 12;
        int r4l = lane >> 2;
        int ltl = lane & 3;
        int n = nb * 8 + r4l;
        int k = kt * 16 + 2 * ltl + 8 * u;
        __half2 hv = __floats2half2_rn(proj_w[n * CCH + k], proj_w[n * CCH + k + 1]);
        g_projw2[j] = *(unsigned*)&hv;
    } else if (i < REPACK_TOTAL) {
        int j2 = i - NQ_ELEMS - NP2_ELEMS;
        int c    = j2 & 3;
        int lane = (j2 >> 2) & 31;
        int t    = j2 >> 7;           // (h*4+mt)*8 + jblk
        int jblk = t & 7;
        int mt   = (t >> 3) & 3;
        int h    = t >> 5;
        int row  = mt * 16 + (lane >> 2) + ((c >= 2) ? 8 : 0);
        int col  = jblk * 8 + 2 * (lane & 3) + (c & 1);
        g_bias2h[j2] = __float2half(bias[(size_t)h * 4096 + row * 64 + col]);
    }
}

using FragA   = wmma::fragment<wmma::matrix_a,16,16,16,__half,wmma::row_major>;
using FragBR  = wmma::fragment<wmma::matrix_b,16,16,16,__half,wmma::row_major>;
using FragCF  = wmma::fragment<wmma::accumulator,16,16,16,float>;
using FragCH  = wmma::fragment<wmma::accumulator,16,16,16,__half>;

// store a float accumulator to half memory (acc layouts match for m16n16k16)
__device__ __forceinline__ void store_acc_half(__half* ptr, int ld, const FragCF& f) {
    FragCH h;
#pragma unroll
    for (int e = 0; e < f.num_elements; ++e) h.x[e] = __float2half(f.x[e]);
    wmma::store_matrix_sync(ptr, h, ld, wmma::mem_row_major);
}

__device__ __forceinline__ void mma16816(float* d,
    unsigned a0, unsigned a1, unsigned a2, unsigned a3,
    unsigned b0, unsigned b1)
{
    asm volatile(
        "mma.sync.aligned.m16n8k16.row.col.f32.f16.f16.f32 "
        "{%0,%1,%2,%3}, {%4,%5,%6,%7}, {%8,%9}, {%0,%1,%2,%3};"
        : "+f"(d[0]), "+f"(d[1]), "+f"(d[2]), "+f"(d[3])
        : "r"(a0), "r"(a1), "r"(a2), "r"(a3), "r"(b0), "r"(b1));
}

__device__ __forceinline__ void ldsm_x4(
    unsigned& r0, unsigned& r1, unsigned& r2, unsigned& r3, unsigned addr)
{
    asm volatile(
        "ldmatrix.sync.aligned.m8n8.x4.shared.b16 {%0,%1,%2,%3}, [%4];"
        : "=r"(r0), "=r"(r1), "=r"(r2), "=r"(r3) : "r"(addr));
}

__device__ __forceinline__ void ldsm_x4_trans(
    unsigned& r0, unsigned& r1, unsigned& r2, unsigned& r3, unsigned addr)
{
    asm volatile(
        "ldmatrix.sync.aligned.m8n8.x4.trans.shared.b16 {%0,%1,%2,%3}, [%4];"
        : "=r"(r0), "=r"(r1), "=r"(r2), "=r"(r3) : "r"(addr));
}

__global__ __launch_bounds__(NTHREADS, 2)
void win_attn_kernel(const float* __restrict__ x,
                     const float* __restrict__ proj_b,
                     float* __restrict__ out)
{
    extern __shared__ __half smem[];
    __half* qkvs = smem;                  // [64][QK_LD] q|k|v half; q cols reused for attn out
    __half* scr  = smem + 64 * QK_LD;     // x window staging

    const int tid  = threadIdx.x;
    const int wid  = tid >> 5;            // 0..5
    const int lane = tid & 31;
    const int r4   = lane >> 2;           // 0..7
    const int lt   = lane & 3;            // 0..3

    const int w   = blockIdx.x;
    const int b   = w >> 10;
    const int rem = w & 1023;
    const int wh  = rem >> 5;
    const int ww  = rem & 31;

    // ---- load x window (64 x 192) as half + augmentation cols ----
    {
        const float* xb = x + (size_t)b * 65536 * CCH;
        for (int i = tid; i < 64 * 48; i += NTHREADS) {
            int r  = i / 48;
            int c4 = i % 48;
            int iy = wh * 8 + (r >> 3);
            int ix = ww * 8 + (r & 7);
            float4 v = *(const float4*)(xb + (size_t)(iy * 256 + ix) * CCH + c4 * 4);
            __half2* d = (__half2*)(scr + r * XS_LD + c4 * 4);
            d[0] = __floats2half2_rn(v.x, v.y);
            d[1] = __floats2half2_rn(v.z, v.w);
        }
        // aug cols 192..207: col 192 = 1.0, rest 0
        for (int i = tid; i < 64 * 2; i += NTHREADS) {
            int r  = i >> 1;
            int g  = i & 1;
            __half2* d = (__half2*)(scr + r * XS_LD + 192 + g * 8);
            __half2 z = __floats2half2_rn(0.0f, 0.0f);
            d[0] = (g == 0) ? __floats2half2_rn(1.0f, 0.0f) : z;
            d[1] = z; d[2] = z; d[3] = z;
        }
    }
    __syncthreads();

    // ---- GEMM1: qkv = x_aug(64x208) @ W_aug^T (bias+scale folded).
    //      6 warps, two passes of (3 gnt x 4 mt); 13 kt steps of 16 ----
#pragma unroll
    for (int pass = 0; pass < 2; ++pass) {
        FragCF acc[3][4];
#pragma unroll
        for (int i = 0; i < 3; ++i)
#pragma unroll
            for (int j = 0; j < 4; ++j) wmma::fill_fragment(acc[i][j], 0.0f);

        const int gnt0 = wid * 3 + pass * 18;
        for (int kt = 0; kt < 13; ++kt) {
            FragA af[4];
#pragma unroll
            for (int j = 0; j < 4; ++j)
                wmma::load_matrix_sync(af[j], scr + j * 16 * XS_LD + kt * 16, XS_LD);
#pragma unroll
            for (int i = 0; i < 3; ++i) {
                FragBR bf;
                wmma::load_matrix_sync(bf, g_qkvw_packed + ((gnt0 + i) * 13 + kt) * 256, 16);
#pragma unroll
                for (int j = 0; j < 4; ++j)
                    wmma::mma_sync(acc[i][j], af[j], bf, acc[i][j]);
            }
        }
#pragma unroll
        for (int i = 0; i < 3; ++i) {
            int gnt = gnt0 + i;
            int h   = gnt / 6;
            int ntl = gnt % 6;
            int col = (ntl >> 1) * 192 + h * 32 + (ntl & 1) * 16;
#pragma unroll
            for (int j = 0; j < 4; ++j)
                store_acc_half(qkvs + j * 16 * QK_LD + col, QK_LD, acc[i][j]);
        }
    }
    __syncthreads();

    // ================= attention middle: warp = head, K/V register-hoisted =================
    // Warp h owns head h completely: K/V fragments loaded ONCE, reused across 4 mt stripes.
    // S and P never touch smem; O written to the warp-private q-column region.
    {
        const int h  = wid;
        const int qo = h * 32;
        const int ko = 192 + h * 32;
        const int vo = 384 + h * 32;

        // hoist K fragments via ldmatrix.x4: kb[kc][j][2]
        unsigned kb[2][8][2];
#pragma unroll
        for (int kc = 0; kc < 2; ++kc)
#pragma unroll
            for (int j2 = 0; j2 < 4; ++j2) {
                // mats: (2j2,klo),(2j2,khi),(2j2+1,klo),(2j2+1,khi)
                int jrow = (2 * j2 + ((lane >> 4) & 1)) * 8 + (lane & 7);
                int kof  = ko + kc * 16 + ((lane >> 3) & 1) * 8;
                const __half* kp = qkvs + jrow * QK_LD + kof;
                unsigned addr = (unsigned)__cvta_generic_to_shared(kp);
                ldsm_x4(kb[kc][2 * j2][0], kb[kc][2 * j2][1],
                        kb[kc][2 * j2 + 1][0], kb[kc][2 * j2 + 1][1], addr);
            }

        // hoist V fragments via ldmatrix.trans: vb[kc][nbh][4]
        unsigned vb[4][2][4];
#pragma unroll
        for (int kc = 0; kc < 4; ++kc)
#pragma unroll
            for (int nbh = 0; nbh < 2; ++nbh) {
                const __half* vp = qkvs + (kc * 16 + (lane & 15)) * QK_LD
                                 + vo + nbh * 16 + (lane >> 4) * 8;
                unsigned addr = (unsigned)__cvta_generic_to_shared(vp);
                ldsm_x4_trans(vb[kc][nbh][0], vb[kc][nbh][1],
                              vb[kc][nbh][2], vb[kc][nbh][3], addr);
            }

#pragma unroll
        for (int mt = 0; mt < 4; ++mt) {
            // ---- logits in registers: S[8 blocks][4], init from half bias ----
            float s[8][4];
            {
                const __half* bp = g_bias2h + (size_t)((h * 4 + mt) * 8) * 128 + lane * 4;
#pragma unroll
                for (int j = 0; j < 8; ++j) {
                    uint2 u = *(const uint2*)(bp + j * 128);
                    float2 f0 = __half22float2(*(__half2*)&u.x);
                    float2 f1 = __half22float2(*(__half2*)&u.y);
                    s[j][0] = f0.x; s[j][1] = f0.y; s[j][2] = f1.x; s[j][3] = f1.y;
                }
                // Q via ldmatrix.x4 (non-trans)
#pragma unroll
                for (int kc = 0; kc < 2; ++kc) {
                    const __half* qp = qkvs + (mt * 16 + (lane & 15)) * QK_LD
                                     + qo + kc * 16 + (lane >> 4) * 8;
                    unsigned addr = (unsigned)__cvta_generic_to_shared(qp);
                    unsigned a0, a1, a2, a3;
                    ldsm_x4(a0, a1, a2, a3, addr);
#pragma unroll
                    for (int j = 0; j < 8; ++j)
                        mma16816(s[j], a0, a1, a2, a3, kb[kc][j][0], kb[kc][j][1]);
                }
            }

            // ---- softmax in registers: rows r4 (c0,c1) and r4+8 (c2,c3) ----
            unsigned pa[8], pb[8];
            {
                float mx0 = -1e30f, mx1 = -1e30f;
#pragma unroll
                for (int j = 0; j < 8; ++j) {
                    mx0 = fmaxf(mx0, fmaxf(s[j][0], s[j][1]));
                    mx1 = fmaxf(mx1, fmaxf(s[j][2], s[j][3]));
                }
                mx0 = fmaxf(mx0, __shfl_xor_sync(0xffffffffu, mx0, 1));
                mx0 = fmaxf(mx0, __shfl_xor_sync(0xffffffffu, mx0, 2));
                mx1 = fmaxf(mx1, __shfl_xor_sync(0xffffffffu, mx1, 1));
                mx1 = fmaxf(mx1, __shfl_xor_sync(0xffffffffu, mx1, 2));
                float s0 = 0.0f, s1 = 0.0f;
#pragma unroll
                for (int j = 0; j < 8; ++j) {
                    s[j][0] = __expf(s[j][0] - mx0);
                    s[j][1] = __expf(s[j][1] - mx0);
                    s[j][2] = __expf(s[j][2] - mx1);
                    s[j][3] = __expf(s[j][3] - mx1);
                    s0 += s[j][0] + s[j][1];
                    s1 += s[j][2] + s[j][3];
                }
                s0 += __shfl_xor_sync(0xffffffffu, s0, 1);
                s0 += __shfl_xor_sync(0xffffffffu, s0, 2);
                s1 += __shfl_xor_sync(0xffffffffu, s1, 1);
                s1 += __shfl_xor_sync(0xffffffffu, s1, 2);
                float i0 = 1.0f / s0, i1 = 1.0f / s1;
#pragma unroll
                for (int j = 0; j < 8; ++j) {
                    __half2 lo = __floats2half2_rn(s[j][0] * i0, s[j][1] * i0);
                    __half2 hi = __floats2half2_rn(s[j][2] * i1, s[j][3] * i1);
                    pa[j] = *(unsigned*)&lo;
                    pb[j] = *(unsigned*)&hi;
                }
            }

            // ---- AV: O(16x32) = P(16x64) @ V(64x32); all operands in registers ----
            {
                float o[4][4];
#pragma unroll
                for (int jn = 0; jn < 4; ++jn)
#pragma unroll
                    for (int c = 0; c < 4; ++c) o[jn][c] = 0.0f;

#pragma unroll
                for (int kc = 0; kc < 4; ++kc) {
                    unsigned a0 = pa[2 * kc],     a1 = pb[2 * kc];
                    unsigned a2 = pa[2 * kc + 1], a3 = pb[2 * kc + 1];
#pragma unroll
                    for (int nbh = 0; nbh < 2; ++nbh) {
                        mma16816(o[nbh * 2 + 0], a0, a1, a2, a3,
                                 vb[kc][nbh][0], vb[kc][nbh][1]);
                        mma16816(o[nbh * 2 + 1], a0, a1, a2, a3,
                                 vb[kc][nbh][2], vb[kc][nbh][3]);
                    }
                }
                // store O to q-region (dead): rows mt*16 + r4 (+8), cols qo + jn*8 + 2*lt
                __half* op = qkvs + (mt * 16 + r4) * QK_LD + qo + 2 * lt;
#pragma unroll
                for (int jn = 0; jn < 4; ++jn) {
                    __half2 lo = __floats2half2_rn(o[jn][0], o[jn][1]);
                    __half2 hi = __floats2half2_rn(o[jn][2], o[jn][3]);
                    *(unsigned*)(op + jn * 8)               = *(unsigned*)&lo;
                    *(unsigned*)(op + jn * 8 + 8 * QK_LD)   = *(unsigned*)&hi;
                }
            }
        }
    }
    __syncthreads();

    // ---- proj: raw mma, direct-global store with proj_b folded into acc init.
    //      warp owns n8-blocks {4w..4w+3} x 4 mt tiles; K=192 (12 kt) ----
    {
        const int nb0 = wid * 4;

        // acc o[nb i][mt j][c]; init with proj_b (c0/c2 = col 2lt, c1/c3 = col 2lt+1)
        float o[4][4][4];
#pragma unroll
        for (int i = 0; i < 4; ++i) {
            float2 pb2 = *(const float2*)(proj_b + (nb0 + i) * 8 + 2 * lt);
#pragma unroll
            for (int j = 0; j < 4; ++j) {
                o[i][j][0] = pb2.x; o[i][j][1] = pb2.y;
                o[i][j][2] = pb2.x; o[i][j][3] = pb2.y;
            }
        }

        for (int kt = 0; kt < 12; ++kt) {
            unsigned a[4][4];
#pragma unroll
            for (int j = 0; j < 4; ++j) {
                const __half* ap = qkvs + (j * 16 + (lane & 15)) * QK_LD
                                 + kt * 16 + (lane >> 4) * 8;
                unsigned addr = (unsigned)__cvta_generic_to_shared(ap);
                ldsm_x4(a[j][0], a[j][1], a[j][2], a[j][3], addr);
            }
#pragma unroll
            for (int i = 0; i < 4; ++i) {
                uint2 bb = *(const uint2*)(g_projw2 + (((nb0 + i) * 12 + kt) * 32 + lane) * 2);
#pragma unroll
                for (int j = 0; j < 4; ++j)
                    mma16816(o[i][j], a[j][0], a[j][1], a[j][2], a[j][3], bb.x, bb.y);
            }
        }

        // direct global store: tile rows split into 2 contiguous 8-token pixel rows.
        // token (16j + r4 + 8*chi) -> pixel row p = 2j + chi, in-row pos r4.
        float* ob = out + ((size_t)b * 65536 + (wh * 8) * 256 + ww * 8) * CCH;
#pragma unroll
        for (int i = 0; i < 4; ++i) {
            int col = (nb0 + i) * 8 + 2 * lt;
#pragma unroll
            for (int j = 0; j < 4; ++j) {
                float* p0 = ob + (size_t)(2 * j)     * 49152 + r4 * CCH + col;
                float* p1 = ob + (size_t)(2 * j + 1) * 49152 + r4 * CCH + col;
                *(float2*)p0 = make_float2(o[i][j][0], o[i][j][1]);
                *(float2*)p1 = make_float2(o[i][j][2], o[i][j][3]);
            }
        }
    }
}

extern "C" void kernel_launch(void* const* d_in, const int* in_sizes, int n_in,
                              void* d_out, int out_size)
{
    const float* x      = (const float*)d_in[0];
    const float* qkv_w  = (const float*)d_in[1];
    const float* qkv_b  = (const float*)d_in[2];
    const float* proj_w = (const float*)d_in[3];
    const float* proj_b = (const float*)d_in[4];
    const float* bias   = (const float*)d_in[5];
    float* out = (float*)d_out;

    repack_kernel<<<(REPACK_TOTAL + 255) / 256, 256>>>(qkv_w, qkv_b, proj_w, bias);

    cudaFuncSetAttribute(win_attn_kernel,
                         cudaFuncAttributeMaxDynamicSharedMemorySize, SMEM_BYTES);
    win_attn_kernel<<<NWIN, NTHREADS, SMEM_BYTES>>>(x, proj_b, out);
}

// round 15
// speedup vs baseline: 8.3574x; 1.0266x over previous
#include <cuda_runtime.h>
#include <cuda_fp16.h>

#define NWIN 4096       // 4 * 32 * 32 windows
#define CCH  192
#define NTHREADS 192    // 6 warps, 2 CTAs/SM

// all strides in HALF elements
#define XS_LD  216      // x augmented to 208 cols (192 + 16 aug) + pad
#define QK_LD  592      // qkv 576 cols + pad; word stride 296 (== 8 mod 32 -> uniform 2-way)

#define SCR_HALFS (64 * XS_LD)             // x staging
#define SMEM_HALFS (64 * QK_LD + SCR_HALFS)
#define SMEM_BYTES (SMEM_HALFS * 2)        // 103424 B -> 2 CTAs/SM

// qkv weights in raw m16n8k16 B-operand per-lane layout:
// [nblk(72 n8-blocks = gnt*2+nbu)][kt(13)][lane(32)][2 unsigned]
// bias row folded at k==192 (aug ones-col), softmax scale folded into q
__device__ unsigned g_qkvw2[72 * 13 * 64];
// proj weights in raw m16n8k16 B-operand per-lane layout:
// [nb(24 n8-blocks)][kt(12)][lane(32)][2 unsigned]
__device__ unsigned g_projw2[24 * 12 * 64];
// bias in m16n8 fp32-accumulator per-lane layout, stored as HALF:
// [h(6)][mt(4)][j(8 n8-blocks)][lane(32)][c(4)]  = 24576 halves
__device__ __half g_bias2h[6 * 4 * 8 * 128];

#define NQ2_ELEMS (72 * 13 * 64)           // 59904 (unsigned)
#define NP2_ELEMS (24 * 12 * 64)           // 18432 (unsigned)
#define NB_ELEMS  (6 * 4 * 8 * 128)        // 24576
#define REPACK_TOTAL (NQ2_ELEMS + NP2_ELEMS + NB_ELEMS)   // 102912

__global__ void repack_kernel(const float* __restrict__ qkv_w,
                              const float* __restrict__ qkv_b,
                              const float* __restrict__ proj_w,
                              const float* __restrict__ bias)
{
    int i = blockIdx.x * blockDim.x + threadIdx.x;
    const float scale = 0.17677669529663687f; // 1/sqrt(32)
    if (i < NQ2_ELEMS) {
        int u    = i & 1;
        int lane = (i >> 1) & 31;
        int t    = i >> 6;            // nblk*13 + kt
        int kt   = t % 13;
        int nblk = t / 13;
        int gnt  = nblk >> 1;
        int nbu  = nblk & 1;
        int h    = gnt / 6;
        int ntl  = gnt % 6;
        int blk  = ntl >> 1;          // 0=q,1=k,2=v
        int wrow = blk * 192 + h * 32 + (ntl & 1) * 16 + nbu * 8 + (lane >> 2);
        int k    = kt * 16 + 2 * (lane & 3) + 8 * u;
        float lo, hi;
        lo = (k < 192)   ? qkv_w[wrow * CCH + k]     : ((k == 192) ? qkv_b[wrow] : 0.0f);
        hi = (k+1 < 192) ? qkv_w[wrow * CCH + k + 1] : ((k+1 == 192) ? qkv_b[wrow] : 0.0f);
        if (blk == 0) { lo *= scale; hi *= scale; }
        __half2 hv = __floats2half2_rn(lo, hi);
        g_qkvw2[i] = *(unsigned*)&hv;
    } else if (i < NQ2_ELEMS + NP2_ELEMS) {
        int j  = i - NQ2_ELEMS;
        int u    = j & 1;
        int lane = (j >> 1) & 31;
        int t    = j >> 6;            // nb*12 + kt
        int kt = t % 12;
        int nb = t / 12;
        int n = nb * 8 + (lane >> 2);
        int k = kt * 16 + 2 * (lane & 3) + 8 * u;
        __half2 hv = __floats2half2_rn(proj_w[n * CCH + k], proj_w[n * CCH + k + 1]);
        g_projw2[j] = *(unsigned*)&hv;
    } else if (i < REPACK_TOTAL) {
        int j2 = i - NQ2_ELEMS - NP2_ELEMS;
        int c    = j2 & 3;
        int lane = (j2 >> 2) & 31;
        int t    = j2 >> 7;           // (h*4+mt)*8 + jblk
        int jblk = t & 7;
        int mt   = (t >> 3) & 3;
        int h    = t >> 5;
        int row  = mt * 16 + (lane >> 2) + ((c >= 2) ? 8 : 0);
        int col  = jblk * 8 + 2 * (lane & 3) + (c & 1);
        g_bias2h[j2] = __float2half(bias[(size_t)h * 4096 + row * 64 + col]);
    }
}

__device__ __forceinline__ void mma16816(float* d,
    unsigned a0, unsigned a1, unsigned a2, unsigned a3,
    unsigned b0, unsigned b1)
{
    asm volatile(
        "mma.sync.aligned.m16n8k16.row.col.f32.f16.f16.f32 "
        "{%0,%1,%2,%3}, {%4,%5,%6,%7}, {%8,%9}, {%0,%1,%2,%3};"
        : "+f"(d[0]), "+f"(d[1]), "+f"(d[2]), "+f"(d[3])
        : "r"(a0), "r"(a1), "r"(a2), "r"(a3), "r"(b0), "r"(b1));
}

__device__ __forceinline__ void ldsm_x4(
    unsigned& r0, unsigned& r1, unsigned& r2, unsigned& r3, unsigned addr)
{
    asm volatile(
        "ldmatrix.sync.aligned.m8n8.x4.shared.b16 {%0,%1,%2,%3}, [%4];"
        : "=r"(r0), "=r"(r1), "=r"(r2), "=r"(r3) : "r"(addr));
}

__device__ __forceinline__ void ldsm_x4_trans(
    unsigned& r0, unsigned& r1, unsigned& r2, unsigned& r3, unsigned addr)
{
    asm volatile(
        "ldmatrix.sync.aligned.m8n8.x4.trans.shared.b16 {%0,%1,%2,%3}, [%4];"
        : "=r"(r0), "=r"(r1), "=r"(r2), "=r"(r3) : "r"(addr));
}

__device__ __forceinline__ void stsm_x4(unsigned addr,
    unsigned r0, unsigned r1, unsigned r2, unsigned r3)
{
    asm volatile(
        "stmatrix.sync.aligned.m8n8.x4.shared.b16 [%0], {%1,%2,%3,%4};"
        :: "r"(addr), "r"(r0), "r"(r1), "r"(r2), "r"(r3) : "memory");
}

__device__ __forceinline__ unsigned packh2(float a, float b) {
    __half2 h = __floats2half2_rn(a, b);
    return *(unsigned*)&h;
}

__global__ __launch_bounds__(NTHREADS, 2)
void win_attn_kernel(const float* __restrict__ x,
                     const float* __restrict__ proj_b,
                     float* __restrict__ out)
{
    extern __shared__ __half smem[];
    __half* qkvs = smem;                  // [64][QK_LD] q|k|v half; q cols reused for attn out
    __half* scr  = smem + 64 * QK_LD;     // x window staging

    const int tid  = threadIdx.x;
    const int wid  = tid >> 5;            // 0..5
    const int lane = tid & 31;
    const int r4   = lane >> 2;           // 0..7
    const int lt   = lane & 3;            // 0..3

    const int w   = blockIdx.x;
    const int b   = w >> 10;
    const int rem = w & 1023;
    const int wh  = rem >> 5;
    const int ww  = rem & 31;

    // ---- load x window (64 x 192) as half + augmentation cols ----
    {
        const float* xb = x + (size_t)b * 65536 * CCH;
        for (int i = tid; i < 64 * 48; i += NTHREADS) {
            int r  = i / 48;
            int c4 = i % 48;
            int iy = wh * 8 + (r >> 3);
            int ix = ww * 8 + (r & 7);
            float4 v = *(const float4*)(xb + (size_t)(iy * 256 + ix) * CCH + c4 * 4);
            __half2* d = (__half2*)(scr + r * XS_LD + c4 * 4);
            d[0] = __floats2half2_rn(v.x, v.y);
            d[1] = __floats2half2_rn(v.z, v.w);
        }
        // aug cols 192..207: col 192 = 1.0, rest 0
        for (int i = tid; i < 64 * 2; i += NTHREADS) {
            int r  = i >> 1;
            int g  = i & 1;
            __half2* d = (__half2*)(scr + r * XS_LD + 192 + g * 8);
            __half2 z = __floats2half2_rn(0.0f, 0.0f);
            d[0] = (g == 0) ? __floats2half2_rn(1.0f, 0.0f) : z;
            d[1] = z; d[2] = z; d[3] = z;
        }
    }
    __syncthreads();

    // ---- GEMM1 (raw mma): qkv = x_aug(64x208) @ W_aug^T, bias+scale folded.
    //      2 passes; per pass warp owns 3 gnt (6 n8-blocks) x 4 mt; 13 kt steps.
    //      A via ldmatrix from scr, B via per-lane uint2 LDG, store via stmatrix ----
#pragma unroll
    for (int pass = 0; pass < 2; ++pass) {
        const int gnt0 = wid * 3 + pass * 18;

        float acc[6][4][4];
#pragma unroll
        for (int i = 0; i < 6; ++i)
#pragma unroll
            for (int j = 0; j < 4; ++j)
#pragma unroll
                for (int c = 0; c < 4; ++c) acc[i][j][c] = 0.0f;

        for (int kt = 0; kt < 13; ++kt) {
            unsigned a[4][4];
#pragma unroll
            for (int j = 0; j < 4; ++j) {
                const __half* ap = scr + (j * 16 + (lane & 15)) * XS_LD
                                 + kt * 16 + (lane >> 4) * 8;
                unsigned addr = (unsigned)__cvta_generic_to_shared(ap);
                ldsm_x4(a[j][0], a[j][1], a[j][2], a[j][3], addr);
            }
#pragma unroll
            for (int i = 0; i < 6; ++i) {
                uint2 bb = *(const uint2*)(g_qkvw2 + (((gnt0 * 2 + i) * 13 + kt) * 32 + lane) * 2);
#pragma unroll
                for (int j = 0; j < 4; ++j)
                    mma16816(acc[i][j], a[j][0], a[j][1], a[j][2], a[j][3], bb.x, bb.y);
            }
        }

        // store: per gnt tile t (2 n8-blocks) x mt j, one stmatrix.x4
#pragma unroll
        for (int t = 0; t < 3; ++t) {
            int gnt = gnt0 + t;
            int h   = gnt / 6;
            int ntl = gnt % 6;
            int col = (ntl >> 1) * 192 + h * 32 + (ntl & 1) * 16;
#pragma unroll
            for (int j = 0; j < 4; ++j) {
                // mats: (blk0 rows0-7), (blk0 rows8-15), (blk1 rows0-7), (blk1 rows8-15)
                unsigned m0 = packh2(acc[2*t  ][j][0], acc[2*t  ][j][1]);
                unsigned m1 = packh2(acc[2*t  ][j][2], acc[2*t  ][j][3]);
                unsigned m2 = packh2(acc[2*t+1][j][0], acc[2*t+1][j][1]);
                unsigned m3 = packh2(acc[2*t+1][j][2], acc[2*t+1][j][3]);
                int row = j * 16 + (lane & 7) + ((lane >> 3) & 1) * 8;
                int cc  = col + (lane >> 4) * 8;
                unsigned addr = (unsigned)__cvta_generic_to_shared(qkvs + row * QK_LD + cc);
                stsm_x4(addr, m0, m1, m2, m3);
            }
        }
    }
    __syncthreads();

    // ================= attention middle: warp = head, K/V register-hoisted =================
    {
        const int h  = wid;
        const int qo = h * 32;
        const int ko = 192 + h * 32;
        const int vo = 384 + h * 32;

        // hoist K fragments via ldmatrix.x4: kb[kc][j][2]
        unsigned kb[2][8][2];
#pragma unroll
        for (int kc = 0; kc < 2; ++kc)
#pragma unroll
            for (int j2 = 0; j2 < 4; ++j2) {
                int jrow = (2 * j2 + ((lane >> 4) & 1)) * 8 + (lane & 7);
                int kof  = ko + kc * 16 + ((lane >> 3) & 1) * 8;
                const __half* kp = qkvs + jrow * QK_LD + kof;
                unsigned addr = (unsigned)__cvta_generic_to_shared(kp);
                ldsm_x4(kb[kc][2 * j2][0], kb[kc][2 * j2][1],
                        kb[kc][2 * j2 + 1][0], kb[kc][2 * j2 + 1][1], addr);
            }

        // hoist V fragments via ldmatrix.trans: vb[kc][nbh][4]
        unsigned vb[4][2][4];
#pragma unroll
        for (int kc = 0; kc < 4; ++kc)
#pragma unroll
            for (int nbh = 0; nbh < 2; ++nbh) {
                const __half* vp = qkvs + (kc * 16 + (lane & 15)) * QK_LD
                                 + vo + nbh * 16 + (lane >> 4) * 8;
                unsigned addr = (unsigned)__cvta_generic_to_shared(vp);
                ldsm_x4_trans(vb[kc][nbh][0], vb[kc][nbh][1],
                              vb[kc][nbh][2], vb[kc][nbh][3], addr);
            }

#pragma unroll
        for (int mt = 0; mt < 4; ++mt) {
            // ---- logits in registers: S[8 blocks][4], init from half bias ----
            float s[8][4];
            {
                const __half* bp = g_bias2h + (size_t)((h * 4 + mt) * 8) * 128 + lane * 4;
#pragma unroll
                for (int j = 0; j < 8; ++j) {
                    uint2 u = *(const uint2*)(bp + j * 128);
                    float2 f0 = __half22float2(*(__half2*)&u.x);
                    float2 f1 = __half22float2(*(__half2*)&u.y);
                    s[j][0] = f0.x; s[j][1] = f0.y; s[j][2] = f1.x; s[j][3] = f1.y;
                }
#pragma unroll
                for (int kc = 0; kc < 2; ++kc) {
                    const __half* qp = qkvs + (mt * 16 + (lane & 15)) * QK_LD
                                     + qo + kc * 16 + (lane >> 4) * 8;
                    unsigned addr = (unsigned)__cvta_generic_to_shared(qp);
                    unsigned a0, a1, a2, a3;
                    ldsm_x4(a0, a1, a2, a3, addr);
#pragma unroll
                    for (int j = 0; j < 8; ++j)
                        mma16816(s[j], a0, a1, a2, a3, kb[kc][j][0], kb[kc][j][1]);
                }
            }

            // ---- softmax in registers: rows r4 (c0,c1) and r4+8 (c2,c3) ----
            unsigned pa[8], pb[8];
            {
                float mx0 = -1e30f, mx1 = -1e30f;
#pragma unroll
                for (int j = 0; j < 8; ++j) {
                    mx0 = fmaxf(mx0, fmaxf(s[j][0], s[j][1]));
                    mx1 = fmaxf(mx1, fmaxf(s[j][2], s[j][3]));
                }
                mx0 = fmaxf(mx0, __shfl_xor_sync(0xffffffffu, mx0, 1));
                mx0 = fmaxf(mx0, __shfl_xor_sync(0xffffffffu, mx0, 2));
                mx1 = fmaxf(mx1, __shfl_xor_sync(0xffffffffu, mx1, 1));
                mx1 = fmaxf(mx1, __shfl_xor_sync(0xffffffffu, mx1, 2));
                float s0 = 0.0f, s1 = 0.0f;
#pragma unroll
                for (int j = 0; j < 8; ++j) {
                    s[j][0] = __expf(s[j][0] - mx0);
                    s[j][1] = __expf(s[j][1] - mx0);
                    s[j][2] = __expf(s[j][2] - mx1);
                    s[j][3] = __expf(s[j][3] - mx1);
                    s0 += s[j][0] + s[j][1];
                    s1 += s[j][2] + s[j][3];
                }
                s0 += __shfl_xor_sync(0xffffffffu, s0, 1);
                s0 += __shfl_xor_sync(0xffffffffu, s0, 2);
                s1 += __shfl_xor_sync(0xffffffffu, s1, 1);
                s1 += __shfl_xor_sync(0xffffffffu, s1, 2);
                float i0 = 1.0f / s0, i1 = 1.0f / s1;
#pragma unroll
                for (int j = 0; j < 8; ++j) {
                    pa[j] = packh2(s[j][0] * i0, s[j][1] * i0);
                    pb[j] = packh2(s[j][2] * i1, s[j][3] * i1);
                }
            }

            // ---- AV: O(16x32) = P(16x64) @ V(64x32); all operands in registers ----
            {
                float o[4][4];
#pragma unroll
                for (int jn = 0; jn < 4; ++jn)
#pragma unroll
                    for (int c = 0; c < 4; ++c) o[jn][c] = 0.0f;

#pragma unroll
                for (int kc = 0; kc < 4; ++kc) {
                    unsigned a0 = pa[2 * kc],     a1 = pb[2 * kc];
                    unsigned a2 = pa[2 * kc + 1], a3 = pb[2 * kc + 1];
#pragma unroll
                    for (int nbh = 0; nbh < 2; ++nbh) {
                        mma16816(o[nbh * 2 + 0], a0, a1, a2, a3,
                                 vb[kc][nbh][0], vb[kc][nbh][1]);
                        mma16816(o[nbh * 2 + 1], a0, a1, a2, a3,
                                 vb[kc][nbh][2], vb[kc][nbh][3]);
                    }
                }
                // store O (16x32) via 2x stmatrix.x4 into q-region (dead)
#pragma unroll
                for (int g = 0; g < 2; ++g) {
                    int jn = g * 2 + ((lane >> 4) & 1);     // mat pair -> jn
                    int rh = (lane >> 3) & 1;               // row half
                    int row = mt * 16 + (lane & 7) + rh * 8;
                    unsigned addr = (unsigned)__cvta_generic_to_shared(
                        qkvs + row * QK_LD + qo + jn * 8);
                    unsigned m0 = packh2(o[g*2  ][0], o[g*2  ][1]);
                    unsigned m1 = packh2(o[g*2  ][2], o[g*2  ][3]);
                    unsigned m2 = packh2(o[g*2+1][0], o[g*2+1][1]);
                    unsigned m3 = packh2(o[g*2+1][2], o[g*2+1][3]);
                    stsm_x4(addr, m0, m1, m2, m3);
                }
            }
        }
    }
    __syncthreads();

    // ---- proj: raw mma, direct-global store with proj_b folded into acc init.
    //      warp owns n8-blocks {4w..4w+3} x 4 mt tiles; K=192 (12 kt) ----
    {
        const int nb0 = wid * 4;

        float o[4][4][4];
#pragma unroll
        for (int i = 0; i < 4; ++i) {
            float2 pb2 = *(const float2*)(proj_b + (nb0 + i) * 8 + 2 * lt);
#pragma unroll
            for (int j = 0; j < 4; ++j) {
                o[i][j][0] = pb2.x; o[i][j][1] = pb2.y;
                o[i][j][2] = pb2.x; o[i][j][3] = pb2.y;
            }
        }

        for (int kt = 0; kt < 12; ++kt) {
            unsigned a[4][4];
#pragma unroll
            for (int j = 0; j < 4; ++j) {
                const __half* ap = qkvs + (j * 16 + (lane & 15)) * QK_LD
                                 + kt * 16 + (lane >> 4) * 8;
                unsigned addr = (unsigned)__cvta_generic_to_shared(ap);
                ldsm_x4(a[j][0], a[j][1], a[j][2], a[j][3], addr);
            }
#pragma unroll
            for (int i = 0; i < 4; ++i) {
                uint2 bb = *(const uint2*)(g_projw2 + (((nb0 + i) * 12 + kt) * 32 + lane) * 2);
#pragma unroll
                for (int j = 0; j < 4; ++j)
                    mma16816(o[i][j], a[j][0], a[j][1], a[j][2], a[j][3], bb.x, bb.y);
            }
        }

        // direct global store: token (16j + r4 + 8*chi) -> pixel row p = 2j + chi
        float* ob = out + ((size_t)b * 65536 + (wh * 8) * 256 + ww * 8) * CCH;
#pragma unroll
        for (int i = 0; i < 4; ++i) {
            int col = (nb0 + i) * 8 + 2 * lt;
#pragma unroll
            for (int j = 0; j < 4; ++j) {
                float* p0 = ob + (size_t)(2 * j)     * 49152 + r4 * CCH + col;
                float* p1 = ob + (size_t)(2 * j + 1) * 49152 + r4 * CCH + col;
                *(float2*)p0 = make_float2(o[i][j][0], o[i][j][1]);
                *(float2*)p1 = make_float2(o[i][j][2], o[i][j][3]);
            }
        }
    }
}

extern "C" void kernel_launch(void* const* d_in, const int* in_sizes, int n_in,
                              void* d_out, int out_size)
{
    const float* x      = (const float*)d_in[0];
    const float* qkv_w  = (const float*)d_in[1];
    const float* qkv_b  = (const float*)d_in[2];
    const float* proj_w = (const float*)d_in[3];
    const float* proj_b = (const float*)d_in[4];
    const float* bias   = (const float*)d_in[5];
    float* out = (float*)d_out;

    repack_kernel<<<(REPACK_TOTAL + 255) / 256, 256>>>(qkv_w, qkv_b, proj_w, bias);

    cudaFuncSetAttribute(win_attn_kernel,
                         cudaFuncAttributeMaxDynamicSharedMemorySize, SMEM_BYTES);
    win_attn_kernel<<<NWIN, NTHREADS, SMEM_BYTES>>>(x, proj_b, out);
}

// round 16
// speedup vs baseline: 9.0923x; 1.0879x over previous
#include <cuda_runtime.h>
#include <cuda_fp16.h>

#define NWIN 4096       // 4 * 32 * 32 windows
#define CCH  192
#define NTHREADS 256    // 8 warps, 2 CTAs/SM

// all strides in HALF elements
#define XS_LD  216      // x augmented to 208 cols (192 + 16 aug) + pad
#define QK_LD  592      // qkv 576 cols + pad; word stride 296 (== 8 mod 32 -> uniform 2-way)

#define SCR_HALFS (64 * XS_LD)             // x staging
#define SMEM_HALFS (64 * QK_LD + SCR_HALFS)
#define SMEM_BYTES (SMEM_HALFS * 2)        // 103424 B -> 2 CTAs/SM

// qkv weights in raw m16n8k16 B-operand per-lane layout:
// [nblk(72 n8-blocks = gnt*2+nbu)][kt(13)][lane(32)][2 unsigned]
__device__ unsigned g_qkvw2[72 * 13 * 64];
// proj weights: [nb(24)][kt(12)][lane(32)][2 unsigned]
__device__ unsigned g_projw2[24 * 12 * 64];
// bias in m16n8 fp32-accumulator per-lane layout, stored as HALF:
// [h(6)][mt(4)][j(8 n8-blocks)][lane(32)][c(4)]
__device__ __half g_bias2h[6 * 4 * 8 * 128];

#define NQ2_ELEMS (72 * 13 * 64)           // 59904 (unsigned)
#define NP2_ELEMS (24 * 12 * 64)           // 18432 (unsigned)
#define NB_ELEMS  (6 * 4 * 8 * 128)        // 24576
#define REPACK_TOTAL (NQ2_ELEMS + NP2_ELEMS + NB_ELEMS)   // 102912

__global__ void repack_kernel(const float* __restrict__ qkv_w,
                              const float* __restrict__ qkv_b,
                              const float* __restrict__ proj_w,
                              const float* __restrict__ bias)
{
    int i = blockIdx.x * blockDim.x + threadIdx.x;
    const float scale = 0.17677669529663687f; // 1/sqrt(32)
    if (i < NQ2_ELEMS) {
        int u    = i & 1;
        int lane = (i >> 1) & 31;
        int t    = i >> 6;            // nblk*13 + kt
        int kt   = t % 13;
        int nblk = t / 13;
        int gnt  = nblk >> 1;
        int nbu  = nblk & 1;
        int h    = gnt / 6;
        int ntl  = gnt % 6;
        int blk  = ntl >> 1;          // 0=q,1=k,2=v
        int wrow = blk * 192 + h * 32 + (ntl & 1) * 16 + nbu * 8 + (lane >> 2);
        int k    = kt * 16 + 2 * (lane & 3) + 8 * u;
        float lo, hi;
        lo = (k < 192)   ? qkv_w[wrow * CCH + k]     : ((k == 192) ? qkv_b[wrow] : 0.0f);
        hi = (k+1 < 192) ? qkv_w[wrow * CCH + k + 1] : ((k+1 == 192) ? qkv_b[wrow] : 0.0f);
        if (blk == 0) { lo *= scale; hi *= scale; }
        __half2 hv = __floats2half2_rn(lo, hi);
        g_qkvw2[i] = *(unsigned*)&hv;
    } else if (i < NQ2_ELEMS + NP2_ELEMS) {
        int j  = i - NQ2_ELEMS;
        int u    = j & 1;
        int lane = (j >> 1) & 31;
        int t    = j >> 6;            // nb*12 + kt
        int kt = t % 12;
        int nb = t / 12;
        int n = nb * 8 + (lane >> 2);
        int k = kt * 16 + 2 * (lane & 3) + 8 * u;
        __half2 hv = __floats2half2_rn(proj_w[n * CCH + k], proj_w[n * CCH + k + 1]);
        g_projw2[j] = *(unsigned*)&hv;
    } else if (i < REPACK_TOTAL) {
        int j2 = i - NQ2_ELEMS - NP2_ELEMS;
        int c    = j2 & 3;
        int lane = (j2 >> 2) & 31;
        int t    = j2 >> 7;           // (h*4+mt)*8 + jblk
        int jblk = t & 7;
        int mt   = (t >> 3) & 3;
        int h    = t >> 5;
        int row  = mt * 16 + (lane >> 2) + ((c >= 2) ? 8 : 0);
        int col  = jblk * 8 + 2 * (lane & 3) + (c & 1);
        g_bias2h[j2] = __float2half(bias[(size_t)h * 4096 + row * 64 + col]);
    }
}

__device__ __forceinline__ void mma16816(float* d,
    unsigned a0, unsigned a1, unsigned a2, unsigned a3,
    unsigned b0, unsigned b1)
{
    asm volatile(
        "mma.sync.aligned.m16n8k16.row.col.f32.f16.f16.f32 "
        "{%0,%1,%2,%3}, {%4,%5,%6,%7}, {%8,%9}, {%0,%1,%2,%3};"
        : "+f"(d[0]), "+f"(d[1]), "+f"(d[2]), "+f"(d[3])
        : "r"(a0), "r"(a1), "r"(a2), "r"(a3), "r"(b0), "r"(b1));
}

__device__ __forceinline__ void ldsm_x4(
    unsigned& r0, unsigned& r1, unsigned& r2, unsigned& r3, unsigned addr)
{
    asm volatile(
        "ldmatrix.sync.aligned.m8n8.x4.shared.b16 {%0,%1,%2,%3}, [%4];"
        : "=r"(r0), "=r"(r1), "=r"(r2), "=r"(r3) : "r"(addr));
}

__device__ __forceinline__ void ldsm_x4_trans(
    unsigned& r0, unsigned& r1, unsigned& r2, unsigned& r3, unsigned addr)
{
    asm volatile(
        "ldmatrix.sync.aligned.m8n8.x4.trans.shared.b16 {%0,%1,%2,%3}, [%4];"
        : "=r"(r0), "=r"(r1), "=r"(r2), "=r"(r3) : "r"(addr));
}

__device__ __forceinline__ void stsm_x2(unsigned addr, unsigned r0, unsigned r1)
{
    asm volatile(
        "stmatrix.sync.aligned.m8n8.x2.shared.b16 [%0], {%1,%2};"
        :: "r"(addr), "r"(r0), "r"(r1) : "memory");
}

__device__ __forceinline__ void stsm_x4(unsigned addr,
    unsigned r0, unsigned r1, unsigned r2, unsigned r3)
{
    asm volatile(
        "stmatrix.sync.aligned.m8n8.x4.shared.b16 [%0], {%1,%2,%3,%4};"
        :: "r"(addr), "r"(r0), "r"(r1), "r"(r2), "r"(r3) : "memory");
}

__device__ __forceinline__ unsigned packh2(float a, float b) {
    __half2 h = __floats2half2_rn(a, b);
    return *(unsigned*)&h;
}

__global__ __launch_bounds__(NTHREADS, 2)
void win_attn_kernel(const float* __restrict__ x,
                     const float* __restrict__ proj_b,
                     float* __restrict__ out)
{
    extern __shared__ __half smem[];
    __half* qkvs = smem;                  // [64][QK_LD] q|k|v half; q cols reused for attn out
    __half* scr  = smem + 64 * QK_LD;     // x window staging

    const int tid  = threadIdx.x;
    const int wid  = tid >> 5;            // 0..7
    const int lane = tid & 31;
    const int r4   = lane >> 2;           // 0..7
    const int lt   = lane & 3;            // 0..3

    const int w   = blockIdx.x;
    const int b   = w >> 10;
    const int rem = w & 1023;
    const int wh  = rem >> 5;
    const int ww  = rem & 31;

    // ---- load x window (64 x 192) as half + augmentation cols ----
    {
        const float* xb = x + (size_t)b * 65536 * CCH;
        for (int i = tid; i < 64 * 48; i += NTHREADS) {
            int r  = i / 48;
            int c4 = i % 48;
            int iy = wh * 8 + (r >> 3);
            int ix = ww * 8 + (r & 7);
            float4 v = *(const float4*)(xb + (size_t)(iy * 256 + ix) * CCH + c4 * 4);
            __half2* d = (__half2*)(scr + r * XS_LD + c4 * 4);
            d[0] = __floats2half2_rn(v.x, v.y);
            d[1] = __floats2half2_rn(v.z, v.w);
        }
        // aug cols 192..207: col 192 = 1.0, rest 0
        for (int i = tid; i < 64 * 2; i += NTHREADS) {
            int r  = i >> 1;
            int g  = i & 1;
            __half2* d = (__half2*)(scr + r * XS_LD + 192 + g * 8);
            __half2 z = __floats2half2_rn(0.0f, 0.0f);
            d[0] = (g == 0) ? __floats2half2_rn(1.0f, 0.0f) : z;
            d[1] = z; d[2] = z; d[3] = z;
        }
    }
    __syncthreads();

    // ---- GEMM1 (raw mma): qkv = x_aug(64x208) @ W_aug^T, bias+scale folded.
    //      3 passes; per pass warp owns 3 n8-blocks x 4 mt; 13 kt steps.
    //      A via ldmatrix from scr, B via per-lane uint2 LDG, store via stmatrix.x2 ----
#pragma unroll
    for (int pass = 0; pass < 3; ++pass) {
        const int nb0 = wid * 3 + pass * 24;   // first n8-block of this warp

        float acc[3][4][4];
#pragma unroll
        for (int i = 0; i < 3; ++i)
#pragma unroll
            for (int j = 0; j < 4; ++j)
#pragma unroll
                for (int c = 0; c < 4; ++c) acc[i][j][c] = 0.0f;

        for (int kt = 0; kt < 13; ++kt) {
            unsigned a[4][4];
#pragma unroll
            for (int j = 0; j < 4; ++j) {
                const __half* ap = scr + (j * 16 + (lane & 15)) * XS_LD
                                 + kt * 16 + (lane >> 4) * 8;
                unsigned addr = (unsigned)__cvta_generic_to_shared(ap);
                ldsm_x4(a[j][0], a[j][1], a[j][2], a[j][3], addr);
            }
#pragma unroll
            for (int i = 0; i < 3; ++i) {
                uint2 bb = *(const uint2*)(g_qkvw2 + (((nb0 + i) * 13 + kt) * 32 + lane) * 2);
#pragma unroll
                for (int j = 0; j < 4; ++j)
                    mma16816(acc[i][j], a[j][0], a[j][1], a[j][2], a[j][3], bb.x, bb.y);
            }
        }

        // store: per n8-block i x mt j, one stmatrix.x2 (16 rows x 8 cols)
#pragma unroll
        for (int i = 0; i < 3; ++i) {
            int nb  = nb0 + i;
            int gnt = nb >> 1;
            int h   = gnt / 6;
            int ntl = gnt % 6;
            int col = (ntl >> 1) * 192 + h * 32 + (ntl & 1) * 16 + (nb & 1) * 8;
#pragma unroll
            for (int j = 0; j < 4; ++j) {
                unsigned m0 = packh2(acc[i][j][0], acc[i][j][1]);
                unsigned m1 = packh2(acc[i][j][2], acc[i][j][3]);
                int row = j * 16 + (lane & 7) + ((lane >> 3) & 1) * 8;
                unsigned addr = (unsigned)__cvta_generic_to_shared(qkvs + row * QK_LD + col);
                stsm_x2(addr, m0, m1);
            }
        }
    }
    __syncthreads();

    // ================= attention middle: 24 (h, mt) stripe-tasks, 3 per warp ==========
    // task t = wid + 8*k: mt = t&3, h = t>>2. V hoisted per task; K inline LDS;
    // S and P register-resident; O via stmatrix into dead q-region.
#pragma unroll
    for (int task = 0; task < 3; ++task) {
        const int t0 = wid + task * 8;
        const int mt = t0 & 3;
        const int h  = t0 >> 2;
        const int qo = h * 32;
        const int ko = 192 + h * 32;
        const int vo = 384 + h * 32;

        // hoist V fragments via ldmatrix.trans: vb[kc][nbh][4]
        unsigned vb[4][2][4];
#pragma unroll
        for (int kc = 0; kc < 4; ++kc)
#pragma unroll
            for (int nbh = 0; nbh < 2; ++nbh) {
                const __half* vp = qkvs + (kc * 16 + (lane & 15)) * QK_LD
                                 + vo + nbh * 16 + (lane >> 4) * 8;
                unsigned addr = (unsigned)__cvta_generic_to_shared(vp);
                ldsm_x4_trans(vb[kc][nbh][0], vb[kc][nbh][1],
                              vb[kc][nbh][2], vb[kc][nbh][3], addr);
            }

        // ---- logits in registers: S[8 blocks][4], init from half bias ----
        float s[8][4];
        {
            const __half* bp = g_bias2h + (size_t)((h * 4 + mt) * 8) * 128 + lane * 4;
#pragma unroll
            for (int j = 0; j < 8; ++j) {
                uint2 u = *(const uint2*)(bp + j * 128);
                float2 f0 = __half22float2(*(__half2*)&u.x);
                float2 f1 = __half22float2(*(__half2*)&u.y);
                s[j][0] = f0.x; s[j][1] = f0.y; s[j][2] = f1.x; s[j][3] = f1.y;
            }
#pragma unroll
            for (int kc = 0; kc < 2; ++kc) {
                const __half* qp = qkvs + (mt * 16 + (lane & 15)) * QK_LD
                                 + qo + kc * 16 + (lane >> 4) * 8;
                unsigned addr = (unsigned)__cvta_generic_to_shared(qp);
                unsigned a0, a1, a2, a3;
                ldsm_x4(a0, a1, a2, a3, addr);
#pragma unroll
                for (int j = 0; j < 8; ++j) {
                    // K block j inline: rows j*8 + r4, cols ko + kc*16 + 2lt (+8)
                    const __half* kp = qkvs + (j * 8 + r4) * QK_LD + ko + kc * 16 + 2 * lt;
                    unsigned b0 = *(const unsigned*)(kp);
                    unsigned b1 = *(const unsigned*)(kp + 8);
                    mma16816(s[j], a0, a1, a2, a3, b0, b1);
                }
            }
        }

        // ---- softmax in registers: rows r4 (c0,c1) and r4+8 (c2,c3) ----
        unsigned pa[8], pb[8];
        {
            float mx0 = -1e30f, mx1 = -1e30f;
#pragma unroll
            for (int j = 0; j < 8; ++j) {
                mx0 = fmaxf(mx0, fmaxf(s[j][0], s[j][1]));
                mx1 = fmaxf(mx1, fmaxf(s[j][2], s[j][3]));
            }
            mx0 = fmaxf(mx0, __shfl_xor_sync(0xffffffffu, mx0, 1));
            mx0 = fmaxf(mx0, __shfl_xor_sync(0xffffffffu, mx0, 2));
            mx1 = fmaxf(mx1, __shfl_xor_sync(0xffffffffu, mx1, 1));
            mx1 = fmaxf(mx1, __shfl_xor_sync(0xffffffffu, mx1, 2));
            float s0 = 0.0f, s1 = 0.0f;
#pragma unroll
            for (int j = 0; j < 8; ++j) {
                s[j][0] = __expf(s[j][0] - mx0);
                s[j][1] = __expf(s[j][1] - mx0);
                s[j][2] = __expf(s[j][2] - mx1);
                s[j][3] = __expf(s[j][3] - mx1);
                s0 += s[j][0] + s[j][1];
                s1 += s[j][2] + s[j][3];
            }
            s0 += __shfl_xor_sync(0xffffffffu, s0, 1);
            s0 += __shfl_xor_sync(0xffffffffu, s0, 2);
            s1 += __shfl_xor_sync(0xffffffffu, s1, 1);
            s1 += __shfl_xor_sync(0xffffffffu, s1, 2);
            float i0 = 1.0f / s0, i1 = 1.0f / s1;
#pragma unroll
            for (int j = 0; j < 8; ++j) {
                pa[j] = packh2(s[j][0] * i0, s[j][1] * i0);
                pb[j] = packh2(s[j][2] * i1, s[j][3] * i1);
            }
        }

        // ---- AV: O(16x32) = P(16x64) @ V(64x32); all operands in registers ----
        {
            float o[4][4];
#pragma unroll
            for (int jn = 0; jn < 4; ++jn)
#pragma unroll
                for (int c = 0; c < 4; ++c) o[jn][c] = 0.0f;

#pragma unroll
            for (int kc = 0; kc < 4; ++kc) {
                unsigned a0 = pa[2 * kc],     a1 = pb[2 * kc];
                unsigned a2 = pa[2 * kc + 1], a3 = pb[2 * kc + 1];
#pragma unroll
                for (int nbh = 0; nbh < 2; ++nbh) {
                    mma16816(o[nbh * 2 + 0], a0, a1, a2, a3,
                             vb[kc][nbh][0], vb[kc][nbh][1]);
                    mma16816(o[nbh * 2 + 1], a0, a1, a2, a3,
                             vb[kc][nbh][2], vb[kc][nbh][3]);
                }
            }
            // store O (16x32) via 2x stmatrix.x4 into q-region (dead)
#pragma unroll
            for (int g = 0; g < 2; ++g) {
                int jn = g * 2 + ((lane >> 4) & 1);
                int rh = (lane >> 3) & 1;
                int row = mt * 16 + (lane & 7) + rh * 8;
                unsigned addr = (unsigned)__cvta_generic_to_shared(
                    qkvs + row * QK_LD + qo + jn * 8);
                unsigned m0 = packh2(o[g*2  ][0], o[g*2  ][1]);
                unsigned m1 = packh2(o[g*2  ][2], o[g*2  ][3]);
                unsigned m2 = packh2(o[g*2+1][0], o[g*2+1][1]);
                unsigned m3 = packh2(o[g*2+1][2], o[g*2+1][3]);
                stsm_x4(addr, m0, m1, m2, m3);
            }
        }
    }
    __syncthreads();

    // ---- proj: raw mma, direct-global store with proj_b folded into acc init.
    //      warp owns n8-blocks {3w..3w+2} x 4 mt tiles; K=192 (12 kt) ----
    {
        const int nb0 = wid * 3;

        float o[3][4][4];
#pragma unroll
        for (int i = 0; i < 3; ++i) {
            float2 pb2 = *(const float2*)(proj_b + (nb0 + i) * 8 + 2 * lt);
#pragma unroll
            for (int j = 0; j < 4; ++j) {
                o[i][j][0] = pb2.x; o[i][j][1] = pb2.y;
                o[i][j][2] = pb2.x; o[i][j][3] = pb2.y;
            }
        }

        for (int kt = 0; kt < 12; ++kt) {
            unsigned a[4][4];
#pragma unroll
            for (int j = 0; j < 4; ++j) {
                const __half* ap = qkvs + (j * 16 + (lane & 15)) * QK_LD
                                 + kt * 16 + (lane >> 4) * 8;
                unsigned addr = (unsigned)__cvta_generic_to_shared(ap);
                ldsm_x4(a[j][0], a[j][1], a[j][2], a[j][3], addr);
            }
#pragma unroll
            for (int i = 0; i < 3; ++i) {
                uint2 bb = *(const uint2*)(g_projw2 + (((nb0 + i) * 12 + kt) * 32 + lane) * 2);
#pragma unroll
                for (int j = 0; j < 4; ++j)
                    mma16816(o[i][j], a[j][0], a[j][1], a[j][2], a[j][3], bb.x, bb.y);
            }
        }

        // direct global store: token (16j + r4 + 8*chi) -> pixel row p = 2j + chi
        float* ob = out + ((size_t)b * 65536 + (wh * 8) * 256 + ww * 8) * CCH;
#pragma unroll
        for (int i = 0; i < 3; ++i) {
            int col = (nb0 + i) * 8 + 2 * lt;
#pragma unroll
            for (int j = 0; j < 4; ++j) {
                float* p0 = ob + (size_t)(2 * j)     * 49152 + r4 * CCH + col;
                float* p1 = ob + (size_t)(2 * j + 1) * 49152 + r4 * CCH + col;
                *(float2*)p0 = make_float2(o[i][j][0], o[i][j][1]);
                *(float2*)p1 = make_float2(o[i][j][2], o[i][j][3]);
            }
        }
    }
}

extern "C" void kernel_launch(void* const* d_in, const int* in_sizes, int n_in,
                              void* d_out, int out_size)
{
    const float* x      = (const float*)d_in[0];
    const float* qkv_w  = (const float*)d_in[1];
    const float* qkv_b  = (const float*)d_in[2];
    const float* proj_w = (const float*)d_in[3];
    const float* proj_b = (const float*)d_in[4];
    const float* bias   = (const float*)d_in[5];
    float* out = (float*)d_out;

    repack_kernel<<<(REPACK_TOTAL + 255) / 256, 256>>>(qkv_w, qkv_b, proj_w, bias);

    cudaFuncSetAttribute(win_attn_kernel,
                         cudaFuncAttributeMaxDynamicSharedMemorySize, SMEM_BYTES);
    win_attn_kernel<<<NWIN, NTHREADS, SMEM_BYTES>>>(x, proj_b, out);
}

// round 17
// speedup vs baseline: 10.0729x; 1.1078x over previous
#include <cuda_runtime.h>
#include <cuda_fp16.h>

#define NWIN 4096       // 4 * 32 * 32 windows
#define CCH  192
#define NTHREADS 256    // 8 warps, 2 CTAs/SM

// all strides in HALF elements
#define XS_LD  216      // x augmented to 208 cols; word stride 108 == 12 mod 32 (ldsm-clean)
#define QK_LD  584      // qkv 576 cols + pad; word stride 292 == 4 mod 32 -> ldmatrix/stmatrix
                        // row segments tile all 32 banks perfectly (conflict-free)

#define SCR_HALFS (64 * XS_LD)             // x staging
#define SMEM_HALFS (64 * QK_LD + SCR_HALFS)
#define SMEM_BYTES (SMEM_HALFS * 2)        // 102400 B -> 2 CTAs/SM

// qkv weights in raw m16n8k16 B-operand per-lane layout:
// [nblk(72 n8-blocks = gnt*2+nbu)][kt(13)][lane(32)][2 unsigned]
__device__ unsigned g_qkvw2[72 * 13 * 64];
// proj weights: [nb(24)][kt(12)][lane(32)][2 unsigned]
__device__ unsigned g_projw2[24 * 12 * 64];
// bias in m16n8 fp32-accumulator per-lane layout, stored as HALF:
// [h(6)][mt(4)][j(8 n8-blocks)][lane(32)][c(4)]
__device__ __half g_bias2h[6 * 4 * 8 * 128];

#define NQ2_ELEMS (72 * 13 * 64)           // 59904 (unsigned)
#define NP2_ELEMS (24 * 12 * 64)           // 18432 (unsigned)
#define NB_ELEMS  (6 * 4 * 8 * 128)        // 24576
#define REPACK_TOTAL (NQ2_ELEMS + NP2_ELEMS + NB_ELEMS)   // 102912

__global__ void repack_kernel(const float* __restrict__ qkv_w,
                              const float* __restrict__ qkv_b,
                              const float* __restrict__ proj_w,
                              const float* __restrict__ bias)
{
    int i = blockIdx.x * blockDim.x + threadIdx.x;
    const float scale = 0.17677669529663687f; // 1/sqrt(32)
    if (i < NQ2_ELEMS) {
        int u    = i & 1;
        int lane = (i >> 1) & 31;
        int t    = i >> 6;            // nblk*13 + kt
        int kt   = t % 13;
        int nblk = t / 13;
        int gnt  = nblk >> 1;
        int nbu  = nblk & 1;
        int h    = gnt / 6;
        int ntl  = gnt % 6;
        int blk  = ntl >> 1;          // 0=q,1=k,2=v
        int wrow = blk * 192 + h * 32 + (ntl & 1) * 16 + nbu * 8 + (lane >> 2);
        int k    = kt * 16 + 2 * (lane & 3) + 8 * u;
        float lo, hi;
        lo = (k < 192)   ? qkv_w[wrow * CCH + k]     : ((k == 192) ? qkv_b[wrow] : 0.0f);
        hi = (k+1 < 192) ? qkv_w[wrow * CCH + k + 1] : ((k+1 == 192) ? qkv_b[wrow] : 0.0f);
        if (blk == 0) { lo *= scale; hi *= scale; }
        __half2 hv = __floats2half2_rn(lo, hi);
        g_qkvw2[i] = *(unsigned*)&hv;
    } else if (i < NQ2_ELEMS + NP2_ELEMS) {
        int j  = i - NQ2_ELEMS;
        int u    = j & 1;
        int lane = (j >> 1) & 31;
        int t    = j >> 6;            // nb*12 + kt
        int kt = t % 12;
        int nb = t / 12;
        int n = nb * 8 + (lane >> 2);
        int k = kt * 16 + 2 * (lane & 3) + 8 * u;
        __half2 hv = __floats2half2_rn(proj_w[n * CCH + k], proj_w[n * CCH + k + 1]);
        g_projw2[j] = *(unsigned*)&hv;
    } else if (i < REPACK_TOTAL) {
        int j2 = i - NQ2_ELEMS - NP2_ELEMS;
        int c    = j2 & 3;
        int lane = (j2 >> 2) & 31;
        int t    = j2 >> 7;           // (h*4+mt)*8 + jblk
        int jblk = t & 7;
        int mt   = (t >> 3) & 3;
        int h    = t >> 5;
        int row  = mt * 16 + (lane >> 2) + ((c >= 2) ? 8 : 0);
        int col  = jblk * 8 + 2 * (lane & 3) + (c & 1);
        g_bias2h[j2] = __float2half(bias[(size_t)h * 4096 + row * 64 + col]);
    }
}

__device__ __forceinline__ void mma16816(float* d,
    unsigned a0, unsigned a1, unsigned a2, unsigned a3,
    unsigned b0, unsigned b1)
{
    asm volatile(
        "mma.sync.aligned.m16n8k16.row.col.f32.f16.f16.f32 "
        "{%0,%1,%2,%3}, {%4,%5,%6,%7}, {%8,%9}, {%0,%1,%2,%3};"
        : "+f"(d[0]), "+f"(d[1]), "+f"(d[2]), "+f"(d[3])
        : "r"(a0), "r"(a1), "r"(a2), "r"(a3), "r"(b0), "r"(b1));
}

__device__ __forceinline__ void ldsm_x4(
    unsigned& r0, unsigned& r1, unsigned& r2, unsigned& r3, unsigned addr)
{
    asm volatile(
        "ldmatrix.sync.aligned.m8n8.x4.shared.b16 {%0,%1,%2,%3}, [%4];"
        : "=r"(r0), "=r"(r1), "=r"(r2), "=r"(r3) : "r"(addr));
}

__device__ __forceinline__ void ldsm_x4_trans(
    unsigned& r0, unsigned& r1, unsigned& r2, unsigned& r3, unsigned addr)
{
    asm volatile(
        "ldmatrix.sync.aligned.m8n8.x4.trans.shared.b16 {%0,%1,%2,%3}, [%4];"
        : "=r"(r0), "=r"(r1), "=r"(r2), "=r"(r3) : "r"(addr));
}

__device__ __forceinline__ void stsm_x2(unsigned addr, unsigned r0, unsigned r1)
{
    asm volatile(
        "stmatrix.sync.aligned.m8n8.x2.shared.b16 [%0], {%1,%2};"
        :: "r"(addr), "r"(r0), "r"(r1) : "memory");
}

__device__ __forceinline__ void stsm_x4(unsigned addr,
    unsigned r0, unsigned r1, unsigned r2, unsigned r3)
{
    asm volatile(
        "stmatrix.sync.aligned.m8n8.x4.shared.b16 [%0], {%1,%2,%3,%4};"
        :: "r"(addr), "r"(r0), "r"(r1), "r"(r2), "r"(r3) : "memory");
}

__device__ __forceinline__ unsigned packh2(float a, float b) {
    __half2 h = __floats2half2_rn(a, b);
    return *(unsigned*)&h;
}

__global__ __launch_bounds__(NTHREADS, 2)
void win_attn_kernel(const float* __restrict__ x,
                     const float* __restrict__ proj_b,
                     float* __restrict__ out)
{
    extern __shared__ __half smem[];
    __half* qkvs = smem;                  // [64][QK_LD] q|k|v half; q cols reused for attn out
    __half* scr  = smem + 64 * QK_LD;     // x window staging

    const int tid  = threadIdx.x;
    const int wid  = tid >> 5;            // 0..7
    const int lane = tid & 31;
    const int r4   = lane >> 2;           // 0..7
    const int lt   = lane & 3;            // 0..3

    const int w   = blockIdx.x;
    const int b   = w >> 10;
    const int rem = w & 1023;
    const int wh  = rem >> 5;
    const int ww  = rem & 31;

    // ---- load x window (64 x 192) as half + augmentation cols ----
    {
        const float* xb = x + (size_t)b * 65536 * CCH;
        for (int i = tid; i < 64 * 48; i += NTHREADS) {
            int r  = i / 48;
            int c4 = i % 48;
            int iy = wh * 8 + (r >> 3);
            int ix = ww * 8 + (r & 7);
            float4 v = *(const float4*)(xb + (size_t)(iy * 256 + ix) * CCH + c4 * 4);
            __half2* d = (__half2*)(scr + r * XS_LD + c4 * 4);
            d[0] = __floats2half2_rn(v.x, v.y);
            d[1] = __floats2half2_rn(v.z, v.w);
        }
        // aug cols 192..207: col 192 = 1.0, rest 0
        for (int i = tid; i < 64 * 2; i += NTHREADS) {
            int r  = i >> 1;
            int g  = i & 1;
            __half2* d = (__half2*)(scr + r * XS_LD + 192 + g * 8);
            __half2 z = __floats2half2_rn(0.0f, 0.0f);
            d[0] = (g == 0) ? __floats2half2_rn(1.0f, 0.0f) : z;
            d[1] = z; d[2] = z; d[3] = z;
        }
    }
    __syncthreads();

    // ---- GEMM1 (raw mma): qkv = x_aug(64x208) @ W_aug^T, bias+scale folded.
    //      3 passes; per pass warp owns 3 n8-blocks x 4 mt; 13 kt steps.
    //      A via ldmatrix from scr, B via per-lane uint2 LDG, store via stmatrix.x2 ----
#pragma unroll
    for (int pass = 0; pass < 3; ++pass) {
        const int nb0 = wid * 3 + pass * 24;   // first n8-block of this warp

        float acc[3][4][4];
#pragma unroll
        for (int i = 0; i < 3; ++i)
#pragma unroll
            for (int j = 0; j < 4; ++j)
#pragma unroll
                for (int c = 0; c < 4; ++c) acc[i][j][c] = 0.0f;

        for (int kt = 0; kt < 13; ++kt) {
            unsigned a[4][4];
#pragma unroll
            for (int j = 0; j < 4; ++j) {
                const __half* ap = scr + (j * 16 + (lane & 15)) * XS_LD
                                 + kt * 16 + (lane >> 4) * 8;
                unsigned addr = (unsigned)__cvta_generic_to_shared(ap);
                ldsm_x4(a[j][0], a[j][1], a[j][2], a[j][3], addr);
            }
#pragma unroll
            for (int i = 0; i < 3; ++i) {
                uint2 bb = *(const uint2*)(g_qkvw2 + (((nb0 + i) * 13 + kt) * 32 + lane) * 2);
#pragma unroll
                for (int j = 0; j < 4; ++j)
                    mma16816(acc[i][j], a[j][0], a[j][1], a[j][2], a[j][3], bb.x, bb.y);
            }
        }

        // store: per n8-block i x mt j, one stmatrix.x2 (16 rows x 8 cols)
#pragma unroll
        for (int i = 0; i < 3; ++i) {
            int nb  = nb0 + i;
            int gnt = nb >> 1;
            int h   = gnt / 6;
            int ntl = gnt % 6;
            int col = (ntl >> 1) * 192 + h * 32 + (ntl & 1) * 16 + (nb & 1) * 8;
#pragma unroll
            for (int j = 0; j < 4; ++j) {
                unsigned m0 = packh2(acc[i][j][0], acc[i][j][1]);
                unsigned m1 = packh2(acc[i][j][2], acc[i][j][3]);
                int row = j * 16 + (lane & 7) + ((lane >> 3) & 1) * 8;
                unsigned addr = (unsigned)__cvta_generic_to_shared(qkvs + row * QK_LD + col);
                stsm_x2(addr, m0, m1);
            }
        }
    }
    __syncthreads();

    // ================= attention middle: 24 (h, mt) stripe-tasks, 3 per warp ==========
    // task t = wid + 8*k: mt = t&3, h = t>>2. V hoisted per task; K inline LDS
    // (conflict-free under word-stride 292); S and P register-resident;
    // O via stmatrix into dead q-region.
#pragma unroll
    for (int task = 0; task < 3; ++task) {
        const int t0 = wid + task * 8;
        const int mt = t0 & 3;
        const int h  = t0 >> 2;
        const int qo = h * 32;
        const int ko = 192 + h * 32;
        const int vo = 384 + h * 32;

        // hoist V fragments via ldmatrix.trans: vb[kc][nbh][4]
        unsigned vb[4][2][4];
#pragma unroll
        for (int kc = 0; kc < 4; ++kc)
#pragma unroll
            for (int nbh = 0; nbh < 2; ++nbh) {
                const __half* vp = qkvs + (kc * 16 + (lane & 15)) * QK_LD
                                 + vo + nbh * 16 + (lane >> 4) * 8;
                unsigned addr = (unsigned)__cvta_generic_to_shared(vp);
                ldsm_x4_trans(vb[kc][nbh][0], vb[kc][nbh][1],
                              vb[kc][nbh][2], vb[kc][nbh][3], addr);
            }

        // ---- logits in registers: S[8 blocks][4], init from half bias ----
        float s[8][4];
        {
            const __half* bp = g_bias2h + (size_t)((h * 4 + mt) * 8) * 128 + lane * 4;
#pragma unroll
            for (int j = 0; j < 8; ++j) {
                uint2 u = *(const uint2*)(bp + j * 128);
                float2 f0 = __half22float2(*(__half2*)&u.x);
                float2 f1 = __half22float2(*(__half2*)&u.y);
                s[j][0] = f0.x; s[j][1] = f0.y; s[j][2] = f1.x; s[j][3] = f1.y;
            }
#pragma unroll
            for (int kc = 0; kc < 2; ++kc) {
                const __half* qp = qkvs + (mt * 16 + (lane & 15)) * QK_LD
                                 + qo + kc * 16 + (lane >> 4) * 8;
                unsigned addr = (unsigned)__cvta_generic_to_shared(qp);
                unsigned a0, a1, a2, a3;
                ldsm_x4(a0, a1, a2, a3, addr);
#pragma unroll
                for (int j = 0; j < 8; ++j) {
                    // K block j inline: rows j*8 + r4, cols ko + kc*16 + 2lt (+8)
                    const __half* kp = qkvs + (j * 8 + r4) * QK_LD + ko + kc * 16 + 2 * lt;
                    unsigned b0 = *(const unsigned*)(kp);
                    unsigned b1 = *(const unsigned*)(kp + 8);
                    mma16816(s[j], a0, a1, a2, a3, b0, b1);
                }
            }
        }

        // ---- softmax in registers: rows r4 (c0,c1) and r4+8 (c2,c3) ----
        unsigned pa[8], pb[8];
        {
            float mx0 = -1e30f, mx1 = -1e30f;
#pragma unroll
            for (int j = 0; j < 8; ++j) {
                mx0 = fmaxf(mx0, fmaxf(s[j][0], s[j][1]));
                mx1 = fmaxf(mx1, fmaxf(s[j][2], s[j][3]));
            }
            mx0 = fmaxf(mx0, __shfl_xor_sync(0xffffffffu, mx0, 1));
            mx0 = fmaxf(mx0, __shfl_xor_sync(0xffffffffu, mx0, 2));
            mx1 = fmaxf(mx1, __shfl_xor_sync(0xffffffffu, mx1, 1));
            mx1 = fmaxf(mx1, __shfl_xor_sync(0xffffffffu, mx1, 2));
            float s0 = 0.0f, s1 = 0.0f;
#pragma unroll
            for (int j = 0; j < 8; ++j) {
                s[j][0] = __expf(s[j][0] - mx0);
                s[j][1] = __expf(s[j][1] - mx0);
                s[j][2] = __expf(s[j][2] - mx1);
                s[j][3] = __expf(s[j][3] - mx1);
                s0 += s[j][0] + s[j][1];
                s1 += s[j][2] + s[j][3];
            }
            s0 += __shfl_xor_sync(0xffffffffu, s0, 1);
            s0 += __shfl_xor_sync(0xffffffffu, s0, 2);
            s1 += __shfl_xor_sync(0xffffffffu, s1, 1);
            s1 += __shfl_xor_sync(0xffffffffu, s1, 2);
            float i0 = 1.0f / s0, i1 = 1.0f / s1;
#pragma unroll
            for (int j = 0; j < 8; ++j) {
                pa[j] = packh2(s[j][0] * i0, s[j][1] * i0);
                pb[j] = packh2(s[j][2] * i1, s[j][3] * i1);
            }
        }

        // ---- AV: O(16x32) = P(16x64) @ V(64x32); all operands in registers ----
        {
            float o[4][4];
#pragma unroll
            for (int jn = 0; jn < 4; ++jn)
#pragma unroll
                for (int c = 0; c < 4; ++c) o[jn][c] = 0.0f;

#pragma unroll
            for (int kc = 0; kc < 4; ++kc) {
                unsigned a0 = pa[2 * kc],     a1 = pb[2 * kc];
                unsigned a2 = pa[2 * kc + 1], a3 = pb[2 * kc + 1];
#pragma unroll
                for (int nbh = 0; nbh < 2; ++nbh) {
                    mma16816(o[nbh * 2 + 0], a0, a1, a2, a3,
                             vb[kc][nbh][0], vb[kc][nbh][1]);
                    mma16816(o[nbh * 2 + 1], a0, a1, a2, a3,
                             vb[kc][nbh][2], vb[kc][nbh][3]);
                }
            }
            // store O (16x32) via 2x stmatrix.x4 into q-region (dead)
#pragma unroll
            for (int g = 0; g < 2; ++g) {
                int jn = g * 2 + ((lane >> 4) & 1);
                int rh = (lane >> 3) & 1;
                int row = mt * 16 + (lane & 7) + rh * 8;
                unsigned addr = (unsigned)__cvta_generic_to_shared(
                    qkvs + row * QK_LD + qo + jn * 8);
                unsigned m0 = packh2(o[g*2  ][0], o[g*2  ][1]);
                unsigned m1 = packh2(o[g*2  ][2], o[g*2  ][3]);
                unsigned m2 = packh2(o[g*2+1][0], o[g*2+1][1]);
                unsigned m3 = packh2(o[g*2+1][2], o[g*2+1][3]);
                stsm_x4(addr, m0, m1, m2, m3);
            }
        }
    }
    __syncthreads();

    // ---- proj: raw mma, direct-global store with proj_b folded into acc init.
    //      warp owns n8-blocks {3w..3w+2} x 4 mt tiles; K=192 (12 kt) ----
    {
        const int nb0 = wid * 3;

        float o[3][4][4];
#pragma unroll
        for (int i = 0; i < 3; ++i) {
            float2 pb2 = *(const float2*)(proj_b + (nb0 + i) * 8 + 2 * lt);
#pragma unroll
            for (int j = 0; j < 4; ++j) {
                o[i][j][0] = pb2.x; o[i][j][1] = pb2.y;
                o[i][j][2] = pb2.x; o[i][j][3] = pb2.y;
            }
        }

        for (int kt = 0; kt < 12; ++kt) {
            unsigned a[4][4];
#pragma unroll
            for (int j = 0; j < 4; ++j) {
                const __half* ap = qkvs + (j * 16 + (lane & 15)) * QK_LD
                                 + kt * 16 + (lane >> 4) * 8;
                unsigned addr = (unsigned)__cvta_generic_to_shared(ap);
                ldsm_x4(a[j][0], a[j][1], a[j][2], a[j][3], addr);
            }
#pragma unroll
            for (int i = 0; i < 3; ++i) {
                uint2 bb = *(const uint2*)(g_projw2 + (((nb0 + i) * 12 + kt) * 32 + lane) * 2);
#pragma unroll
                for (int j = 0; j < 4; ++j)
                    mma16816(o[i][j], a[j][0], a[j][1], a[j][2], a[j][3], bb.x, bb.y);
            }
        }

        // direct global store: token (16j + r4 + 8*chi) -> pixel row p = 2j + chi
        float* ob = out + ((size_t)b * 65536 + (wh * 8) * 256 + ww * 8) * CCH;
#pragma unroll
        for (int i = 0; i < 3; ++i) {
            int col = (nb0 + i) * 8 + 2 * lt;
#pragma unroll
            for (int j = 0; j < 4; ++j) {
                float* p0 = ob + (size_t)(2 * j)     * 49152 + r4 * CCH + col;
                float* p1 = ob + (size_t)(2 * j + 1) * 49152 + r4 * CCH + col;
                *(float2*)p0 = make_float2(o[i][j][0], o[i][j][1]);
                *(float2*)p1 = make_float2(o[i][j][2], o[i][j][3]);
            }
        }
    }
}

extern "C" void kernel_launch(void* const* d_in, const int* in_sizes, int n_in,
                              void* d_out, int out_size)
{
    const float* x      = (const float*)d_in[0];
    const float* qkv_w  = (const float*)d_in[1];
    const float* qkv_b  = (const float*)d_in[2];
    const float* proj_w = (const float*)d_in[3];
    const float* proj_b = (const float*)d_in[4];
    const float* bias   = (const float*)d_in[5];
    float* out = (float*)d_out;

    repack_kernel<<<(REPACK_TOTAL + 255) / 256, 256>>>(qkv_w, qkv_b, proj_w, bias);

    cudaFuncSetAttribute(win_attn_kernel,
                         cudaFuncAttributeMaxDynamicSharedMemorySize, SMEM_BYTES);
    win_attn_kernel<<<NWIN, NTHREADS, SMEM_BYTES>>>(x, proj_b, out);
}